// round 10
// baseline (speedup 1.0000x reference)
#include <cuda_runtime.h>
#include <cuda_fp16.h>
#include <cstdint>

#define CIN 512
#define SEQ 1024

// ---------------- scratch ----------------
__device__ __half g_W16[3 * 512 * 1024];             // [w][c][h*64+d] scale-folded
__device__ __half g_Wo16[1024 * 512];                // [j'=v*64+d][c] permuted fp16 Wo
__device__ __half g_Qh[2 * 16 * 1024 * 64];          // [b][h][s][d]
__device__ __half g_Kh[2 * 16 * 1024 * 64];          // [b][h][s][d]
__device__ __half g_Vh[2 * 16 * 1024 * 64];          // [b][h][k][d]
__device__ __half g_J[(size_t)2 * 16 * 1024 * 1024]; // [b][h][q][k] 64 MB
__device__ __half g_U[(size_t)2 * 16 * 1024 * 1024]; // [b][v][q][k] 64 MB (x256)
__device__ __half g_Oh[2 * 1024 * 1024];             // [b][q][v*64+d] fp16

#define USCALE 256.0f
#define UINV   (1.0f / 256.0f)

// ---------------- exp via MUFU ----------------
__device__ __forceinline__ float fast_exp(float x) {
    float r;
    asm("ex2.approx.f32 %0, %1;" : "=f"(r) : "f"(x * 1.4426950408889634f));
    return r;
}

// ---------------- mma helpers ----------------
__device__ __forceinline__ uint32_t cvta_s(const void* p) {
    return (uint32_t)__cvta_generic_to_shared(p);
}
__device__ __forceinline__ void ldm4(uint32_t* r, uint32_t a) {
    asm volatile("ldmatrix.sync.aligned.m8n8.x4.shared.b16 {%0,%1,%2,%3}, [%4];"
        : "=r"(r[0]), "=r"(r[1]), "=r"(r[2]), "=r"(r[3]) : "r"(a));
}
__device__ __forceinline__ void ldm4t(uint32_t* r, uint32_t a) {
    asm volatile("ldmatrix.sync.aligned.m8n8.x4.trans.shared.b16 {%0,%1,%2,%3}, [%4];"
        : "=r"(r[0]), "=r"(r[1]), "=r"(r[2]), "=r"(r[3]) : "r"(a));
}
__device__ __forceinline__ void mma16816(float* c, const uint32_t* a, const uint32_t* b) {
    asm volatile("mma.sync.aligned.m16n8k16.row.col.f32.f16.f16.f32 "
        "{%0,%1,%2,%3}, {%4,%5,%6,%7}, {%8,%9}, {%0,%1,%2,%3};"
        : "+f"(c[0]), "+f"(c[1]), "+f"(c[2]), "+f"(c[3])
        : "r"(a[0]), "r"(a[1]), "r"(a[2]), "r"(a[3]), "r"(b[0]), "r"(b[1]));
}

// convert 16 fp32 -> 16 fp16 (two uint4)
__device__ __forceinline__ void cvt16(const float4* f, uint4* o) {
    __half h[16];
#pragma unroll
    for (int i = 0; i < 4; i++) {
        h[i * 4 + 0] = __float2half_rn(f[i].x);
        h[i * 4 + 1] = __float2half_rn(f[i].y);
        h[i * 4 + 2] = __float2half_rn(f[i].z);
        h[i * 4 + 3] = __float2half_rn(f[i].w);
    }
    o[0] = ((uint4*)h)[0];
    o[1] = ((uint4*)h)[1];
}

// ================= KC0: weight reorders only =================
__global__ __launch_bounds__(256) void kc0(
        const float* __restrict__ Wq, const float* __restrict__ Wk,
        const float* __restrict__ Wv,
        const float* __restrict__ aq, const float* __restrict__ ak,
        const float* __restrict__ av, const float* __restrict__ Wo) {
    int bid = blockIdx.x, tid = threadIdx.x;
    if (bid < 192) {
        __shared__ __half sT[8 * 1024];
        int w = bid >> 6, r0 = (bid & 63) * 8;
        const float* W = (w == 0) ? Wq : ((w == 1) ? Wk : Wv);
        float al = (w == 0) ? aq[0] : ((w == 1) ? ak[0] : av[0]);
        float sc = 1.0f / (1.0f + fast_exp(-al));
#pragma unroll
        for (int i = 0; i < 8; i++) {
            int idx = i * 256 + tid;
            int row = idx >> 8, col4 = (idx & 255) * 4;
            float4 v = *(const float4*)&W[(r0 + row) * 1024 + col4];
            __half* d = &sT[row * 1024 + col4];
            d[0] = __float2half_rn(v.x * sc);
            d[1] = __float2half_rn(v.y * sc);
            d[2] = __float2half_rn(v.z * sc);
            d[3] = __float2half_rn(v.w * sc);
        }
        __syncthreads();
#pragma unroll
        for (int i = 0; i < 4; i++) {
            int idx = i * 256 + tid;
            int row = idx >> 7, jo8 = (idx & 127) * 8;
            __half outv[8];
#pragma unroll
            for (int e = 0; e < 8; e++) {
                int jp = jo8 + e;
                outv[e] = sT[row * 1024 + (jp & 63) * 16 + (jp >> 6)];
            }
            *(uint4*)&g_W16[w * 524288 + (r0 + row) * 1024 + jo8] = *(uint4*)outv;
        }
        return;
    }
    {
        int u2 = (bid - 192) * 256 + tid;
        int jp = u2 >> 8, cp = (u2 & 255) * 2;
        int wrow = ((jp & 63) << 4) | (jp >> 6);
        *(__half2*)(g_Wo16 + jp * 512 + cp) =
            __floats2half2_rn(Wo[wrow * 512 + cp], Wo[wrow * 512 + cp + 1]);
    }
}

// ================= K1: QKV projection, HMMA, 128x128, KC=32 DB, staged epilogue ====
// A loaded from fp32 inp directly (converted in-flight)
__global__ __launch_bounds__(256) void k1_proj(const float* __restrict__ inp) {
    __shared__ __half s1[17408];
    __half* Asb[2] = { s1, s1 + 4352 };
    __half* Bsb[2] = { s1 + 8704, s1 + 13056 };
    int z = blockIdx.z;
    int b = z / 3, w = z % 3;
    int n0 = blockIdx.x * 128, m0 = blockIdx.y * 128;
    const float* AgF = inp + b * 524288;
    const __half* Bg = g_W16 + w * 524288;

    int t = threadIdx.x, lane = t & 31, warp = t >> 5;
    int lrow = t >> 3, lcol = (t & 7) * 16;

    {
        float4 fa[4];
#pragma unroll
        for (int i = 0; i < 4; i++)
            fa[i] = *(const float4*)(AgF + lrow * 1024 + m0 + lcol + i * 4);
        uint4 ap[2];
        cvt16(fa, ap);
        uint4* ad = (uint4*)(Asb[0] + lrow * 136 + lcol);
        ad[0] = ap[0]; ad[1] = ap[1];
        const uint4* bs = (const uint4*)(Bg + lrow * 1024 + n0 + lcol);
        uint4* bd = (uint4*)(Bsb[0] + lrow * 136 + lcol);
        bd[0] = bs[0]; bd[1] = bs[1];
    }
    __syncthreads();

    int wm = (warp >> 2) * 64, wn = (warp & 3) * 32;
    int a_r = (lane & 7) + ((lane & 16) ? 8 : 0);
    int a_c = (lane & 8) ? 8 : 0;
    int b_r = (lane & 7) + ((lane & 8) ? 8 : 0);
    int b_c = (lane & 16) ? 8 : 0;

    float acc[4][4][4] = {};
    for (int ch = 0; ch < 16; ch++) {
        int buf = ch & 1;
        float4 fa[4];
        uint4 pb0, pb1;
        if (ch < 15) {
#pragma unroll
            for (int i = 0; i < 4; i++)
                fa[i] = *(const float4*)(AgF + ((ch + 1) * 32 + lrow) * 1024 + m0 + lcol + i * 4);
            const uint4* bs = (const uint4*)(Bg + ((ch + 1) * 32 + lrow) * 1024 + n0 + lcol);
            pb0 = bs[0]; pb1 = bs[1];
        }
#pragma unroll
        for (int ks = 0; ks < 2; ks++) {
            int kk = ks * 16;
            uint32_t af[4][4], bf[2][4];
#pragma unroll
            for (int mi = 0; mi < 4; mi++)
                ldm4t(af[mi], cvta_s(Asb[buf] + (kk + a_r) * 136 + wm + mi * 16 + a_c));
#pragma unroll
            for (int np = 0; np < 2; np++)
                ldm4t(bf[np], cvta_s(Bsb[buf] + (kk + b_r) * 136 + wn + np * 16 + b_c));
#pragma unroll
            for (int mi = 0; mi < 4; mi++)
#pragma unroll
                for (int ni = 0; ni < 4; ni++)
                    mma16816(acc[mi][ni], af[mi], &bf[ni >> 1][(ni & 1) * 2]);
        }
        if (ch < 15) {
            int nb = buf ^ 1;
            uint4 ap[2];
            cvt16(fa, ap);
            uint4* ad = (uint4*)(Asb[nb] + lrow * 136 + lcol);
            ad[0] = ap[0]; ad[1] = ap[1];
            uint4* bd = (uint4*)(Bsb[nb] + lrow * 136 + lcol);
            bd[0] = pb0; bd[1] = pb1;
        }
        __syncthreads();
    }

    __half* stage = s1;
    int row = lane >> 2, colp = (lane & 3) * 2;
#pragma unroll
    for (int mi = 0; mi < 4; mi++)
#pragma unroll
        for (int ni = 0; ni < 4; ni++) {
            int rr = wm + mi * 16 + row, cc = wn + ni * 8 + colp;
            *(__half2*)&stage[rr * 136 + cc] =
                __floats2half2_rn(acc[mi][ni][0], acc[mi][ni][1]);
            *(__half2*)&stage[(rr + 8) * 136 + cc] =
                __floats2half2_rn(acc[mi][ni][2], acc[mi][ni][3]);
        }
    __syncthreads();

    __half* base = (w == 0) ? g_Qh : ((w == 1) ? g_Kh : g_Vh);
#pragma unroll
    for (int i = 0; i < 8; i++) {
        int idx = i * 256 + t;
        int rr = idx >> 4, chunk = idx & 15;
        int jp = n0 + chunk * 8;
        int h = jp >> 6, d = jp & 63;
        *(uint4*)(base + (((b * 16 + h) * 1024 + m0 + rr) << 6) + d) =
            *(const uint4*)&stage[rr * 136 + chunk * 8];
    }
}

// ================= K2: J = Q.K^T per (b,h), HMMA, K=64 single-shot, staged epilogue =
__global__ __launch_bounds__(256) void k2_J() {
    __shared__ __half s2[18432];
    __half* As = s2;
    __half* Bs = s2 + 9216;
    int bh = blockIdx.z;
    int q0 = blockIdx.y * 128, k0 = blockIdx.x * 128;
    const __half* Qb = g_Qh + ((size_t)bh << 16);
    const __half* Kb = g_Kh + ((size_t)bh << 16);

    int t = threadIdx.x, lane = t & 31, warp = t >> 5;
    {
        int lr = t >> 1, ls = (t & 1) * 32;
        const uint4* qs = (const uint4*)(Qb + ((q0 + lr) << 6) + ls);
        const uint4* ks = (const uint4*)(Kb + ((k0 + lr) << 6) + ls);
        uint4* ad = (uint4*)(As + lr * 72 + ls);
        uint4* bd = (uint4*)(Bs + lr * 72 + ls);
#pragma unroll
        for (int i = 0; i < 4; i++) { ad[i] = qs[i]; bd[i] = ks[i]; }
    }
    __syncthreads();

    int wm = (warp >> 2) * 64, wn = (warp & 3) * 32;
    int amr = lane & 15, akc = (lane >> 4) * 8;
    int bnr = (lane & 7) + ((lane & 16) ? 8 : 0);
    int bkc = (lane & 8) ? 8 : 0;

    float acc[4][4][4] = {};
#pragma unroll
    for (int ks = 0; ks < 4; ks++) {
        int kk = ks * 16;
        uint32_t af[4][4], bf[2][4];
#pragma unroll
        for (int mi = 0; mi < 4; mi++)
            ldm4(af[mi], cvta_s(As + (wm + mi * 16 + amr) * 72 + kk + akc));
#pragma unroll
        for (int np = 0; np < 2; np++)
            ldm4(bf[np], cvta_s(Bs + (wn + np * 16 + bnr) * 72 + kk + bkc));
#pragma unroll
        for (int mi = 0; mi < 4; mi++)
#pragma unroll
            for (int ni = 0; ni < 4; ni++)
                mma16816(acc[mi][ni], af[mi], &bf[ni >> 1][(ni & 1) * 2]);
    }
    __syncthreads();

    __half* stage = s2;
    int row = lane >> 2, colp = (lane & 3) * 2;
#pragma unroll
    for (int mi = 0; mi < 4; mi++)
#pragma unroll
        for (int ni = 0; ni < 4; ni++) {
            int rr = wm + mi * 16 + row, cc = wn + ni * 8 + colp;
            *(__half2*)&stage[rr * 136 + cc] =
                __floats2half2_rn(acc[mi][ni][0], acc[mi][ni][1]);
            *(__half2*)&stage[(rr + 8) * 136 + cc] =
                __floats2half2_rn(acc[mi][ni][2], acc[mi][ni][3]);
        }
    __syncthreads();

    __half* Jp = g_J + ((size_t)bh << 20);
#pragma unroll
    for (int i = 0; i < 8; i++) {
        int idx = i * 256 + t;
        int rr = idx >> 4, chunk = idx & 15;
        *(uint4*)&Jp[(size_t)(q0 + rr) * 1024 + k0 + chunk * 8] =
            *(const uint4*)&stage[rr * 136 + chunk * 8];
    }
}

// ====== K34: per (b,q): EL = J@Wl - mask, softmax over k, U = W@Ww — all HMMA ======
#define JST 1032
__global__ __launch_bounds__(256) void k34_softmax_U(const float* __restrict__ mask,
                                                     const float* __restrict__ Wl,
                                                     const float* __restrict__ Ww) {
    extern __shared__ __half sJ[];
    __shared__ __half sWl[16 * 24];
    __shared__ __half sWwS[16 * 24];
    __shared__ float sMask[1024];
    __shared__ float red[8][16];
    __shared__ float sInv[16];

    int q = blockIdx.x, b = blockIdx.y;
    int tid = threadIdx.x, lane = tid & 31, w = tid >> 5;
    const __half* Jb = g_J + (size_t)b * 16777216 + (size_t)q * 1024;

    { int h = tid >> 4, g = tid & 15; sWl[h * 24 + g] = __float2half(Wl[h * 16 + g]); }
    { float4 m4 = *(const float4*)(mask + b * 1024 + tid * 4);
      *(float4*)&sMask[tid * 4] = m4; }
#pragma unroll
    for (int p = 0; p < 2; p++) {
        int h = w * 2 + p;
        const uint4* src = (const uint4*)(Jb + (size_t)h * 1048576);
#pragma unroll
        for (int it = 0; it < 4; it++)
            *(uint4*)&sJ[h * JST + (lane + it * 32) * 8] = __ldcs(src + lane + it * 32);
    }
    __syncthreads();

    // ---- phase 1 ----
    uint32_t bWl[4];
    {
        int b_r = (lane & 7) + ((lane & 8) ? 8 : 0);
        int b_c = (lane & 16) ? 8 : 0;
        ldm4t(bWl, cvta_s(sWl + b_r * 24 + b_c));
    }
    int a_r = (lane & 7) + ((lane & 16) ? 8 : 0);
    int a_c = (lane & 8) ? 8 : 0;
    int r = lane >> 2, cg = (lane & 3) * 2;
    int kbase = w * 128;
    float psum4[4] = {};
#pragma unroll
    for (int i = 0; i < 8; i++) {
        int kcol = kbase + i * 16;
        uint32_t af[4];
        ldm4t(af, cvta_s(sJ + a_r * JST + kcol + a_c));
        float c0[4] = {}, c1[4] = {};
        mma16816(c0, af, &bWl[0]);
        mma16816(c1, af, &bWl[2]);
        float mk0 = sMask[kcol + r], mk1 = sMask[kcol + r + 8];
        float e00 = fast_exp(c0[0] - mk0), e01 = fast_exp(c0[1] - mk0);
        float e02 = fast_exp(c0[2] - mk1), e03 = fast_exp(c0[3] - mk1);
        float e10 = fast_exp(c1[0] - mk0), e11 = fast_exp(c1[1] - mk0);
        float e12 = fast_exp(c1[2] - mk1), e13 = fast_exp(c1[3] - mk1);
        psum4[0] += e00 + e02; psum4[1] += e01 + e03;
        psum4[2] += e10 + e12; psum4[3] += e11 + e13;
        *(__half2*)&sJ[r * JST + kcol + cg]           = __floats2half2_rn(e00, e01);
        *(__half2*)&sJ[(r + 8) * JST + kcol + cg]     = __floats2half2_rn(e02, e03);
        *(__half2*)&sJ[r * JST + kcol + 8 + cg]       = __floats2half2_rn(e10, e11);
        *(__half2*)&sJ[(r + 8) * JST + kcol + 8 + cg] = __floats2half2_rn(e12, e13);
    }
#pragma unroll
    for (int s = 16; s >= 4; s >>= 1) {
#pragma unroll
        for (int j = 0; j < 4; j++)
            psum4[j] += __shfl_xor_sync(0xffffffffu, psum4[j], s);
    }
    if (lane < 4) {
        red[w][2 * lane]     = psum4[0];
        red[w][2 * lane + 1] = psum4[1];
        red[w][2 * lane + 8] = psum4[2];
        red[w][2 * lane + 9] = psum4[3];
    }
    __syncthreads();
    if (tid < 16) {
        float s = 0.f;
#pragma unroll
        for (int ww = 0; ww < 8; ww++) s += red[ww][tid];
        sInv[tid] = USCALE / s;
    }
    __syncthreads();
    { int v = tid >> 4, g = tid & 15;
      sWwS[v * 24 + g] = __float2half(sInv[g] * Ww[g * 16 + v]); }
    __syncthreads();

    // ---- phase 2 ----
    uint32_t aW[4];
    { int amr = lane & 15, akc2 = (lane >> 4) * 8;
      ldm4(aW, cvta_s(sWwS + amr * 24 + akc2)); }
    int bnr = (lane & 7) + ((lane & 16) ? 8 : 0);
    int bkc = (lane & 8) ? 8 : 0;
#pragma unroll
    for (int i = 0; i < 8; i++) {
        int kcol = kbase + i * 16;
        uint32_t bf[4];
        ldm4(bf, cvta_s(sJ + bnr * JST + kcol + bkc));
        float c0[4] = {}, c1[4] = {};
        mma16816(c0, aW, &bf[0]);
        mma16816(c1, aW, &bf[2]);
        __syncwarp();
        *(__half2*)&sJ[r * JST + kcol + cg]           = __floats2half2_rn(c0[0], c0[1]);
        *(__half2*)&sJ[(r + 8) * JST + kcol + cg]     = __floats2half2_rn(c0[2], c0[3]);
        *(__half2*)&sJ[r * JST + kcol + 8 + cg]       = __floats2half2_rn(c1[0], c1[1]);
        *(__half2*)&sJ[(r + 8) * JST + kcol + 8 + cg] = __floats2half2_rn(c1[2], c1[3]);
    }
    __syncwarp();
    __half* Ub = g_U + (size_t)b * 16777216 + (size_t)q * 1024;
#pragma unroll
    for (int it = 0; it < 8; it++) {
        int idx = lane + it * 32;
        int v = idx >> 4, uu = (idx & 15) * 8;
        __stcs((uint4*)&Ub[(size_t)v * 1048576 + kbase + uu],
               *(const uint4*)&sJ[v * JST + kbase + uu]);
    }
}

// ================= K5: O = U.V per (b,v), HMMA, 128x64, KC=64 DB, fp16 out =========
__global__ __launch_bounds__(256) void k5_O() {
    extern __shared__ __half sm5[];
    __half* Asb[2] = { sm5, sm5 + 128 * 72 };
    __half* Bsb[2] = { sm5 + 2 * 128 * 72, sm5 + 2 * 128 * 72 + 64 * 72 };
    int bv = blockIdx.y;
    int b = bv >> 4, v = bv & 15;
    int q0 = blockIdx.x * 128;
    const __half* U  = g_U + ((size_t)bv << 20);
    const __half* Vb = g_Vh + ((size_t)bv << 16);

    int t = threadIdx.x, lane = t & 31, warp = t >> 5;
    int alr = t >> 1, als = (t & 1) * 32;
    int blr = t >> 2, bls = (t & 3) * 16;

    {
        const uint4* as = (const uint4*)(U + (size_t)(q0 + alr) * 1024 + als);
        const uint4* bs = (const uint4*)(Vb + (blr << 6) + bls);
        uint4* ad = (uint4*)(Asb[0] + alr * 72 + als);
        uint4* bd = (uint4*)(Bsb[0] + blr * 72 + bls);
#pragma unroll
        for (int i = 0; i < 4; i++) ad[i] = __ldcs(as + i);
        bd[0] = bs[0]; bd[1] = bs[1];
    }
    __syncthreads();

    int wm = (warp >> 1) * 32, wn = (warp & 1) * 32;
    int amr = lane & 15, akc = (lane >> 4) * 8;
    int btr = (lane & 7) + ((lane & 8) ? 8 : 0);
    int btc = (lane & 16) ? 8 : 0;

    float acc[2][4][4] = {};
    for (int ch = 0; ch < 16; ch++) {
        int buf = ch & 1;
        uint4 pa[4], pb[2];
        if (ch < 15) {
            int kn = (ch + 1) * 64;
            const uint4* as = (const uint4*)(U + (size_t)(q0 + alr) * 1024 + kn + als);
            const uint4* bs = (const uint4*)(Vb + ((kn + blr) << 6) + bls);
#pragma unroll
            for (int i = 0; i < 4; i++) pa[i] = __ldcs(as + i);
            pb[0] = bs[0]; pb[1] = bs[1];
        }
#pragma unroll
        for (int ks = 0; ks < 4; ks++) {
            int kk = ks * 16;
            uint32_t af[2][4], bf[2][4];
#pragma unroll
            for (int mi = 0; mi < 2; mi++)
                ldm4(af[mi], cvta_s(Asb[buf] + (wm + mi * 16 + amr) * 72 + kk + akc));
#pragma unroll
            for (int np = 0; np < 2; np++)
                ldm4t(bf[np], cvta_s(Bsb[buf] + (kk + btr) * 72 + wn + np * 16 + btc));
#pragma unroll
            for (int mi = 0; mi < 2; mi++)
#pragma unroll
                for (int ni = 0; ni < 4; ni++)
                    mma16816(acc[mi][ni], af[mi], &bf[ni >> 1][(ni & 1) * 2]);
        }
        if (ch < 15) {
            int nb = buf ^ 1;
            uint4* ad = (uint4*)(Asb[nb] + alr * 72 + als);
            uint4* bd = (uint4*)(Bsb[nb] + blr * 72 + bls);
#pragma unroll
            for (int i = 0; i < 4; i++) ad[i] = pa[i];
            bd[0] = pb[0]; bd[1] = pb[1];
        }
        __syncthreads();
    }

    int row = lane >> 2, colp = (lane & 3) * 2;
#pragma unroll
    for (int mi = 0; mi < 2; mi++) {
        int q = q0 + wm + mi * 16 + row;
#pragma unroll
        for (int ni = 0; ni < 4; ni++) {
            int d = wn + ni * 8 + colp;
            __half* p = g_Oh + b * 1048576 + q * 1024 + v * 64 + d;
            *(__half2*)p = __floats2half2_rn(acc[mi][ni][0] * UINV, acc[mi][ni][1] * UINV);
            *(__half2*)(p + 8 * 1024) =
                __floats2half2_rn(acc[mi][ni][2] * UINV, acc[mi][ni][3] * UINV);
        }
    }
}

// ================= K6: out[b,c,q] = inp + O @ Wo16, HMMA 64x128, KC=64 DB ==========
__global__ __launch_bounds__(256) void k6_out(const float* __restrict__ inp,
                                              float* __restrict__ out) {
    extern __shared__ __half sm6[];
    __half* Asb[2] = { sm6, sm6 + 64 * 72 };
    __half* Bsb[2] = { sm6 + 2 * 64 * 72, sm6 + 2 * 64 * 72 + 64 * 136 };
    float* Cs = (float*)sm6;
    int b = blockIdx.z;
    int c0 = blockIdx.x * 128, q0 = blockIdx.y * 64;
    const __half* Oq = g_Oh + b * 1048576;

    int t = threadIdx.x, lane = t & 31, w = t >> 5;
    int alr = t >> 2, als = (t & 3) * 16;
    int blr = t >> 2, bls = (t & 3) * 32;

    {
        const uint4* as = (const uint4*)(Oq + (q0 + alr) * 1024 + als);
        uint4* ad = (uint4*)(Asb[0] + alr * 72 + als);
        ad[0] = as[0]; ad[1] = as[1];
        const uint4* bs = (const uint4*)(g_Wo16 + blr * 512 + c0 + bls);
        uint4* bd = (uint4*)(Bsb[0] + blr * 136 + bls);
        bd[0] = bs[0]; bd[1] = bs[1]; bd[2] = bs[2]; bd[3] = bs[3];
    }
    __syncthreads();

    int wm = (w >> 2) * 32, wn = (w & 3) * 32;
    int amr = lane & 15, akc = (lane >> 4) * 8;
    int b_r = (lane & 7) + ((lane & 8) ? 8 : 0);
    int b_c = (lane & 16) ? 8 : 0;

    float acc[2][4][4] = {};
    for (int ch = 0; ch < 16; ch++) {
        int buf = ch & 1;
        uint4 pa[2], pb[4];
        if (ch < 15) {
            int kn = (ch + 1) * 64;
            const uint4* as = (const uint4*)(Oq + (q0 + alr) * 1024 + kn + als);
            pa[0] = as[0]; pa[1] = as[1];
            const uint4* bs = (const uint4*)(g_Wo16 + (kn + blr) * 512 + c0 + bls);
            pb[0] = bs[0]; pb[1] = bs[1]; pb[2] = bs[2]; pb[3] = bs[3];
        }
#pragma unroll
        for (int ks = 0; ks < 4; ks++) {
            int kk = ks * 16;
            uint32_t af[2][4], bf[2][4];
#pragma unroll
            for (int mi = 0; mi < 2; mi++)
                ldm4(af[mi], cvta_s(Asb[buf] + (wm + mi * 16 + amr) * 72 + kk + akc));
#pragma unroll
            for (int np = 0; np < 2; np++)
                ldm4t(bf[np], cvta_s(Bsb[buf] + (kk + b_r) * 136 + wn + np * 16 + b_c));
#pragma unroll
            for (int mi = 0; mi < 2; mi++)
#pragma unroll
                for (int ni = 0; ni < 4; ni++)
                    mma16816(acc[mi][ni], af[mi], &bf[ni >> 1][(ni & 1) * 2]);
        }
        if (ch < 15) {
            int nb = buf ^ 1;
            uint4* ad = (uint4*)(Asb[nb] + alr * 72 + als);
            ad[0] = pa[0]; ad[1] = pa[1];
            uint4* bd = (uint4*)(Bsb[nb] + blr * 136 + bls);
            bd[0] = pb[0]; bd[1] = pb[1]; bd[2] = pb[2]; bd[3] = pb[3];
        }
        __syncthreads();
    }

    int row = lane >> 2, cp = (lane & 3) * 2;
#pragma unroll
    for (int mi = 0; mi < 2; mi++)
#pragma unroll
        for (int ni = 0; ni < 4; ni++) {
            int qq = wm + mi * 16 + row;
            int cc2 = wn + ni * 8 + cp;
            Cs[cc2 * 68 + qq]           = acc[mi][ni][0];
            Cs[(cc2 + 1) * 68 + qq]     = acc[mi][ni][1];
            Cs[cc2 * 68 + qq + 8]       = acc[mi][ni][2];
            Cs[(cc2 + 1) * 68 + qq + 8] = acc[mi][ni][3];
        }
    __syncthreads();
#pragma unroll
    for (int i2 = 0; i2 < 8; i2++) {
        int idx = t + i2 * 256;
        int cc2 = idx >> 4, q4 = (idx & 15) * 4;
        size_t off = (size_t)b * 524288 + (size_t)(c0 + cc2) * 1024 + q0 + q4;
        float4 iv = *(const float4*)(inp + off);
        *(float4*)(out + off) = make_float4(iv.x + Cs[cc2 * 68 + q4],
                                            iv.y + Cs[cc2 * 68 + q4 + 1],
                                            iv.z + Cs[cc2 * 68 + q4 + 2],
                                            iv.w + Cs[cc2 * 68 + q4 + 3]);
    }
}

// ================= launch =================
extern "C" void kernel_launch(void* const* d_in, const int* in_sizes, int n_in,
                              void* d_out, int out_size) {
    const float* inp  = (const float*)d_in[0];
    const float* mask = (const float*)d_in[1];
    const float* Wq   = (const float*)d_in[2];
    const float* Wk   = (const float*)d_in[3];
    const float* Wv   = (const float*)d_in[4];
    const float* aq   = (const float*)d_in[5];
    const float* ak   = (const float*)d_in[6];
    const float* av   = (const float*)d_in[7];
    const float* Wl   = (const float*)d_in[8];
    const float* Ww   = (const float*)d_in[9];
    const float* Wo   = (const float*)d_in[10];
    float* out = (float*)d_out;

    const int SMEM_K34 = 16 * JST * 2;                        // 33024
    const int SMEM_K5  = (2 * 128 * 72 + 2 * 64 * 72) * 2;    // 55296
    const int SMEM_K6  = (2 * 64 * 72 + 2 * 64 * 136) * 2;    // 53248
    cudaFuncSetAttribute(k34_softmax_U, cudaFuncAttributeMaxDynamicSharedMemorySize, SMEM_K34);
    cudaFuncSetAttribute(k5_O, cudaFuncAttributeMaxDynamicSharedMemorySize, SMEM_K5);
    cudaFuncSetAttribute(k6_out, cudaFuncAttributeMaxDynamicSharedMemorySize, SMEM_K6);

    kc0<<<1216, 256>>>(Wq, Wk, Wv, aq, ak, av, Wo);
    k1_proj<<<dim3(8, 8, 6), 256>>>(inp);
    k2_J<<<dim3(8, 8, 32), 256>>>();
    k34_softmax_U<<<dim3(1024, 2), 256, SMEM_K34>>>(mask, Wl, Ww);
    k5_O<<<dim3(8, 32), 256, SMEM_K5>>>();
    k6_out<<<dim3(4, 16, 2), 256, SMEM_K6>>>(inp, out);
}

// round 12
// speedup vs baseline: 1.0511x; 1.0511x over previous
#include <cuda_runtime.h>
#include <cuda_fp16.h>
#include <cstdint>

#define CIN 512
#define SEQ 1024

// ---------------- scratch ----------------
__device__ __half g_inp16[2 * 512 * 1024];           // [b][c][s]
__device__ __half g_W16[3 * 512 * 1024];             // [w][c][h*64+d] scale-folded
__device__ __half g_Wo16[1024 * 512];                // [j'=v*64+d][c] permuted fp16 Wo
__device__ __half g_Qh[2 * 16 * 1024 * 64];          // [b][h][s][d]
__device__ __half g_Kh[2 * 16 * 1024 * 64];          // [b][h][s][d]
__device__ __half g_Vh[2 * 16 * 1024 * 64];          // [b][h][k][d]
__device__ __half g_J[(size_t)2 * 16 * 1024 * 1024]; // [b][h][q][k] 64 MB
__device__ __half g_U[(size_t)2 * 16 * 1024 * 1024]; // [b][v][q][k] 64 MB (x256)
__device__ __half g_Oh[2 * 1024 * 1024];             // [b][q][v*64+d] fp16

#define USCALE 256.0f
#define UINV   (1.0f / 256.0f)

// ---------------- exp via MUFU ----------------
__device__ __forceinline__ float fast_exp(float x) {
    float r;
    asm("ex2.approx.f32 %0, %1;" : "=f"(r) : "f"(x * 1.4426950408889634f));
    return r;
}

// ---------------- mma helpers ----------------
__device__ __forceinline__ uint32_t cvta_s(const void* p) {
    return (uint32_t)__cvta_generic_to_shared(p);
}
__device__ __forceinline__ void ldm4(uint32_t* r, uint32_t a) {
    asm volatile("ldmatrix.sync.aligned.m8n8.x4.shared.b16 {%0,%1,%2,%3}, [%4];"
        : "=r"(r[0]), "=r"(r[1]), "=r"(r[2]), "=r"(r[3]) : "r"(a));
}
__device__ __forceinline__ void ldm4t(uint32_t* r, uint32_t a) {
    asm volatile("ldmatrix.sync.aligned.m8n8.x4.trans.shared.b16 {%0,%1,%2,%3}, [%4];"
        : "=r"(r[0]), "=r"(r[1]), "=r"(r[2]), "=r"(r[3]) : "r"(a));
}
__device__ __forceinline__ void mma16816(float* c, const uint32_t* a, const uint32_t* b) {
    asm volatile("mma.sync.aligned.m16n8k16.row.col.f32.f16.f16.f32 "
        "{%0,%1,%2,%3}, {%4,%5,%6,%7}, {%8,%9}, {%0,%1,%2,%3};"
        : "+f"(c[0]), "+f"(c[1]), "+f"(c[2]), "+f"(c[3])
        : "r"(a[0]), "r"(a[1]), "r"(a[2]), "r"(a[3]), "r"(b[0]), "r"(b[1]));
}

// ================= KC0: fp16 conversions + weight reorders =================
__global__ __launch_bounds__(256) void kc0(const float* __restrict__ inp,
        const float* __restrict__ Wq, const float* __restrict__ Wk,
        const float* __restrict__ Wv,
        const float* __restrict__ aq, const float* __restrict__ ak,
        const float* __restrict__ av, const float* __restrict__ Wo) {
    int bid = blockIdx.x, tid = threadIdx.x;
    if (bid < 2048) {
        int t = bid * 256 + tid;
        float2 v = *(const float2*)(inp + (size_t)t * 2);
        *(__half2*)(g_inp16 + (size_t)t * 2) = __floats2half2_rn(v.x, v.y);
        return;
    }
    if (bid < 2240) {
        __shared__ __half sT[8 * 1024];
        int u = bid - 2048;
        int w = u >> 6, r0 = (u & 63) * 8;
        const float* W = (w == 0) ? Wq : ((w == 1) ? Wk : Wv);
        float al = (w == 0) ? aq[0] : ((w == 1) ? ak[0] : av[0]);
        float sc = 1.0f / (1.0f + fast_exp(-al));
#pragma unroll
        for (int i = 0; i < 8; i++) {
            int idx = i * 256 + tid;
            int row = idx >> 8, col4 = (idx & 255) * 4;
            float4 v = *(const float4*)&W[(r0 + row) * 1024 + col4];
            __half* d = &sT[row * 1024 + col4];
            d[0] = __float2half_rn(v.x * sc);
            d[1] = __float2half_rn(v.y * sc);
            d[2] = __float2half_rn(v.z * sc);
            d[3] = __float2half_rn(v.w * sc);
        }
        __syncthreads();
#pragma unroll
        for (int i = 0; i < 4; i++) {
            int idx = i * 256 + tid;
            int row = idx >> 7, jo8 = (idx & 127) * 8;
            __half outv[8];
#pragma unroll
            for (int e = 0; e < 8; e++) {
                int jp = jo8 + e;
                outv[e] = sT[row * 1024 + (jp & 63) * 16 + (jp >> 6)];
            }
            *(uint4*)&g_W16[w * 524288 + (r0 + row) * 1024 + jo8] = *(uint4*)outv;
        }
        return;
    }
    {
        int u2 = (bid - 2240) * 256 + tid;
        int jp = u2 >> 8, cp = (u2 & 255) * 2;
        int wrow = ((jp & 63) << 4) | (jp >> 6);
        *(__half2*)(g_Wo16 + jp * 512 + cp) =
            __floats2half2_rn(Wo[wrow * 512 + cp], Wo[wrow * 512 + cp + 1]);
    }
}

// ================= K1: QKV projection, HMMA, 128x128, KC=32 DB, staged epilogue ====
__global__ __launch_bounds__(256) void k1_proj() {
    __shared__ __half s1[17408];
    __half* Asb[2] = { s1, s1 + 4352 };
    __half* Bsb[2] = { s1 + 8704, s1 + 13056 };
    int z = blockIdx.z;
    int b = z / 3, w = z % 3;
    int n0 = blockIdx.x * 128, m0 = blockIdx.y * 128;
    const __half* Ag = g_inp16 + b * 524288;
    const __half* Bg = g_W16 + w * 524288;

    int t = threadIdx.x, lane = t & 31, warp = t >> 5;
    int lrow = t >> 3, lcol = (t & 7) * 16;

    {
        const uint4* as = (const uint4*)(Ag + lrow * 1024 + m0 + lcol);
        const uint4* bs = (const uint4*)(Bg + lrow * 1024 + n0 + lcol);
        uint4* ad = (uint4*)(Asb[0] + lrow * 136 + lcol);
        uint4* bd = (uint4*)(Bsb[0] + lrow * 136 + lcol);
        ad[0] = as[0]; ad[1] = as[1];
        bd[0] = bs[0]; bd[1] = bs[1];
    }
    __syncthreads();

    int wm = (warp >> 2) * 64, wn = (warp & 3) * 32;
    int a_r = (lane & 7) + ((lane & 16) ? 8 : 0);
    int a_c = (lane & 8) ? 8 : 0;
    int b_r = (lane & 7) + ((lane & 8) ? 8 : 0);
    int b_c = (lane & 16) ? 8 : 0;

    float acc[4][4][4] = {};
    for (int ch = 0; ch < 16; ch++) {
        int buf = ch & 1;
        uint4 pa0, pa1, pb0, pb1;
        if (ch < 15) {
            const uint4* as = (const uint4*)(Ag + ((ch + 1) * 32 + lrow) * 1024 + m0 + lcol);
            const uint4* bs = (const uint4*)(Bg + ((ch + 1) * 32 + lrow) * 1024 + n0 + lcol);
            pa0 = as[0]; pa1 = as[1];
            pb0 = bs[0]; pb1 = bs[1];
        }
#pragma unroll
        for (int ks = 0; ks < 2; ks++) {
            int kk = ks * 16;
            uint32_t af[4][4], bf[2][4];
#pragma unroll
            for (int mi = 0; mi < 4; mi++)
                ldm4t(af[mi], cvta_s(Asb[buf] + (kk + a_r) * 136 + wm + mi * 16 + a_c));
#pragma unroll
            for (int np = 0; np < 2; np++)
                ldm4t(bf[np], cvta_s(Bsb[buf] + (kk + b_r) * 136 + wn + np * 16 + b_c));
#pragma unroll
            for (int mi = 0; mi < 4; mi++)
#pragma unroll
                for (int ni = 0; ni < 4; ni++)
                    mma16816(acc[mi][ni], af[mi], &bf[ni >> 1][(ni & 1) * 2]);
        }
        if (ch < 15) {
            int nb = buf ^ 1;
            uint4* ad = (uint4*)(Asb[nb] + lrow * 136 + lcol);
            uint4* bd = (uint4*)(Bsb[nb] + lrow * 136 + lcol);
            ad[0] = pa0; ad[1] = pa1;
            bd[0] = pb0; bd[1] = pb1;
        }
        __syncthreads();
    }

    __half* stage = s1;
    int row = lane >> 2, colp = (lane & 3) * 2;
#pragma unroll
    for (int mi = 0; mi < 4; mi++)
#pragma unroll
        for (int ni = 0; ni < 4; ni++) {
            int rr = wm + mi * 16 + row, cc = wn + ni * 8 + colp;
            *(__half2*)&stage[rr * 136 + cc] =
                __floats2half2_rn(acc[mi][ni][0], acc[mi][ni][1]);
            *(__half2*)&stage[(rr + 8) * 136 + cc] =
                __floats2half2_rn(acc[mi][ni][2], acc[mi][ni][3]);
        }
    __syncthreads();

    __half* base = (w == 0) ? g_Qh : ((w == 1) ? g_Kh : g_Vh);
#pragma unroll
    for (int i = 0; i < 8; i++) {
        int idx = i * 256 + t;
        int rr = idx >> 4, chunk = idx & 15;
        int jp = n0 + chunk * 8;
        int h = jp >> 6, d = jp & 63;
        *(uint4*)(base + (((b * 16 + h) * 1024 + m0 + rr) << 6) + d) =
            *(const uint4*)&stage[rr * 136 + chunk * 8];
    }
}

// ================= K2: J = Q.K^T per (b,h), HMMA, K=64 single-shot, staged epilogue =
__global__ __launch_bounds__(256) void k2_J() {
    __shared__ __half s2[18432];
    __half* As = s2;
    __half* Bs = s2 + 9216;
    int bh = blockIdx.z;
    int q0 = blockIdx.y * 128, k0 = blockIdx.x * 128;
    const __half* Qb = g_Qh + ((size_t)bh << 16);
    const __half* Kb = g_Kh + ((size_t)bh << 16);

    int t = threadIdx.x, lane = t & 31, warp = t >> 5;
    {
        int lr = t >> 1, ls = (t & 1) * 32;
        const uint4* qs = (const uint4*)(Qb + ((q0 + lr) << 6) + ls);
        const uint4* ks = (const uint4*)(Kb + ((k0 + lr) << 6) + ls);
        uint4* ad = (uint4*)(As + lr * 72 + ls);
        uint4* bd = (uint4*)(Bs + lr * 72 + ls);
#pragma unroll
        for (int i = 0; i < 4; i++) { ad[i] = qs[i]; bd[i] = ks[i]; }
    }
    __syncthreads();

    int wm = (warp >> 2) * 64, wn = (warp & 3) * 32;
    int amr = lane & 15, akc = (lane >> 4) * 8;
    int bnr = (lane & 7) + ((lane & 16) ? 8 : 0);
    int bkc = (lane & 8) ? 8 : 0;

    float acc[4][4][4] = {};
#pragma unroll
    for (int ks = 0; ks < 4; ks++) {
        int kk = ks * 16;
        uint32_t af[4][4], bf[2][4];
#pragma unroll
        for (int mi = 0; mi < 4; mi++)
            ldm4(af[mi], cvta_s(As + (wm + mi * 16 + amr) * 72 + kk + akc));
#pragma unroll
        for (int np = 0; np < 2; np++)
            ldm4(bf[np], cvta_s(Bs + (wn + np * 16 + bnr) * 72 + kk + bkc));
#pragma unroll
        for (int mi = 0; mi < 4; mi++)
#pragma unroll
            for (int ni = 0; ni < 4; ni++)
                mma16816(acc[mi][ni], af[mi], &bf[ni >> 1][(ni & 1) * 2]);
    }
    __syncthreads();

    __half* stage = s2;
    int row = lane >> 2, colp = (lane & 3) * 2;
#pragma unroll
    for (int mi = 0; mi < 4; mi++)
#pragma unroll
        for (int ni = 0; ni < 4; ni++) {
            int rr = wm + mi * 16 + row, cc = wn + ni * 8 + colp;
            *(__half2*)&stage[rr * 136 + cc] =
                __floats2half2_rn(acc[mi][ni][0], acc[mi][ni][1]);
            *(__half2*)&stage[(rr + 8) * 136 + cc] =
                __floats2half2_rn(acc[mi][ni][2], acc[mi][ni][3]);
        }
    __syncthreads();

    __half* Jp = g_J + ((size_t)bh << 20);
#pragma unroll
    for (int i = 0; i < 8; i++) {
        int idx = i * 256 + t;
        int rr = idx >> 4, chunk = idx & 15;
        *(uint4*)&Jp[(size_t)(q0 + rr) * 1024 + k0 + chunk * 8] =
            *(const uint4*)&stage[rr * 136 + chunk * 8];
    }
}

// ====== K34: per (b,q): EL = J@Wl - mask, softmax over k, U = W@Ww — all HMMA ======
#define JST 1032
__global__ __launch_bounds__(256) void k34_softmax_U(const float* __restrict__ mask,
                                                     const float* __restrict__ Wl,
                                                     const float* __restrict__ Ww) {
    extern __shared__ __half sJ[];
    __shared__ __half sWl[16 * 24];
    __shared__ __half sWwS[16 * 24];
    __shared__ float sMask[1024];
    __shared__ float red[8][16];
    __shared__ float sInv[16];

    int q = blockIdx.x, b = blockIdx.y;
    int tid = threadIdx.x, lane = tid & 31, w = tid >> 5;
    const __half* Jb = g_J + (size_t)b * 16777216 + (size_t)q * 1024;

    { int h = tid >> 4, g = tid & 15; sWl[h * 24 + g] = __float2half(Wl[h * 16 + g]); }
    { float4 m4 = *(const float4*)(mask + b * 1024 + tid * 4);
      *(float4*)&sMask[tid * 4] = m4; }
#pragma unroll
    for (int p = 0; p < 2; p++) {
        int h = w * 2 + p;
        const uint4* src = (const uint4*)(Jb + (size_t)h * 1048576);
#pragma unroll
        for (int it = 0; it < 4; it++)
            *(uint4*)&sJ[h * JST + (lane + it * 32) * 8] = src[lane + it * 32];
    }
    __syncthreads();

    // ---- phase 1 ----
    uint32_t bWl[4];
    {
        int b_r = (lane & 7) + ((lane & 8) ? 8 : 0);
        int b_c = (lane & 16) ? 8 : 0;
        ldm4t(bWl, cvta_s(sWl + b_r * 24 + b_c));
    }
    int a_r = (lane & 7) + ((lane & 16) ? 8 : 0);
    int a_c = (lane & 8) ? 8 : 0;
    int r = lane >> 2, cg = (lane & 3) * 2;
    int kbase = w * 128;
    float psum4[4] = {};
#pragma unroll
    for (int i = 0; i < 8; i++) {
        int kcol = kbase + i * 16;
        uint32_t af[4];
        ldm4t(af, cvta_s(sJ + a_r * JST + kcol + a_c));
        float c0[4] = {}, c1[4] = {};
        mma16816(c0, af, &bWl[0]);
        mma16816(c1, af, &bWl[2]);
        float mk0 = sMask[kcol + r], mk1 = sMask[kcol + r + 8];
        float e00 = fast_exp(c0[0] - mk0), e01 = fast_exp(c0[1] - mk0);
        float e02 = fast_exp(c0[2] - mk1), e03 = fast_exp(c0[3] - mk1);
        float e10 = fast_exp(c1[0] - mk0), e11 = fast_exp(c1[1] - mk0);
        float e12 = fast_exp(c1[2] - mk1), e13 = fast_exp(c1[3] - mk1);
        psum4[0] += e00 + e02; psum4[1] += e01 + e03;
        psum4[2] += e10 + e12; psum4[3] += e11 + e13;
        *(__half2*)&sJ[r * JST + kcol + cg]           = __floats2half2_rn(e00, e01);
        *(__half2*)&sJ[(r + 8) * JST + kcol + cg]     = __floats2half2_rn(e02, e03);
        *(__half2*)&sJ[r * JST + kcol + 8 + cg]       = __floats2half2_rn(e10, e11);
        *(__half2*)&sJ[(r + 8) * JST + kcol + 8 + cg] = __floats2half2_rn(e12, e13);
    }
#pragma unroll
    for (int s = 16; s >= 4; s >>= 1) {
#pragma unroll
        for (int j = 0; j < 4; j++)
            psum4[j] += __shfl_xor_sync(0xffffffffu, psum4[j], s);
    }
    if (lane < 4) {
        red[w][2 * lane]     = psum4[0];
        red[w][2 * lane + 1] = psum4[1];
        red[w][2 * lane + 8] = psum4[2];
        red[w][2 * lane + 9] = psum4[3];
    }
    __syncthreads();
    if (tid < 16) {
        float s = 0.f;
#pragma unroll
        for (int ww = 0; ww < 8; ww++) s += red[ww][tid];
        sInv[tid] = USCALE / s;
    }
    __syncthreads();
    { int v = tid >> 4, g = tid & 15;
      sWwS[v * 24 + g] = __float2half(sInv[g] * Ww[g * 16 + v]); }
    __syncthreads();

    // ---- phase 2 ----
    uint32_t aW[4];
    { int amr = lane & 15, akc2 = (lane >> 4) * 8;
      ldm4(aW, cvta_s(sWwS + amr * 24 + akc2)); }
    int bnr = (lane & 7) + ((lane & 16) ? 8 : 0);
    int bkc = (lane & 8) ? 8 : 0;
#pragma unroll
    for (int i = 0; i < 8; i++) {
        int kcol = kbase + i * 16;
        uint32_t bf[4];
        ldm4(bf, cvta_s(sJ + bnr * JST + kcol + bkc));
        float c0[4] = {}, c1[4] = {};
        mma16816(c0, aW, &bf[0]);
        mma16816(c1, aW, &bf[2]);
        __syncwarp();
        *(__half2*)&sJ[r * JST + kcol + cg]           = __floats2half2_rn(c0[0], c0[1]);
        *(__half2*)&sJ[(r + 8) * JST + kcol + cg]     = __floats2half2_rn(c0[2], c0[3]);
        *(__half2*)&sJ[r * JST + kcol + 8 + cg]       = __floats2half2_rn(c1[0], c1[1]);
        *(__half2*)&sJ[(r + 8) * JST + kcol + 8 + cg] = __floats2half2_rn(c1[2], c1[3]);
    }
    __syncwarp();
    __half* Ub = g_U + (size_t)b * 16777216 + (size_t)q * 1024;
#pragma unroll
    for (int it = 0; it < 8; it++) {
        int idx = lane + it * 32;
        int v = idx >> 4, uu = (idx & 15) * 8;
        *(uint4*)&Ub[(size_t)v * 1048576 + kbase + uu] =
            *(const uint4*)&sJ[v * JST + kbase + uu];
    }
}

// ================= K5: O = U.V per (b,v), HMMA, 64x64 tiles, KC=64 DB, fp16 out ====
// 64x64 retile: grid 512 blocks, 36 KB smem. Each thread loads 2 consecutive
// uint4 (16 halves) per tile: 256 thr x 2 x 8 halves = 4096 = full 64x64 tile.
__global__ __launch_bounds__(256) void k5_O() {
    extern __shared__ __half sm5[];
    __half* Asb[2] = { sm5, sm5 + 64 * 72 };
    __half* Bsb[2] = { sm5 + 2 * 64 * 72, sm5 + 2 * 64 * 72 + 64 * 72 };
    int bv = blockIdx.y;
    int b = bv >> 4, v = bv & 15;
    int q0 = blockIdx.x * 64;
    const __half* U  = g_U + ((size_t)bv << 20);
    const __half* Vb = g_Vh + ((size_t)bv << 16);

    int t = threadIdx.x, lane = t & 31, warp = t >> 5;
    int lr = t >> 2, ls = (t & 3) * 16;   // row 0..63, col offset {0,16,32,48}

    {
        const uint4* as = (const uint4*)(U + (size_t)(q0 + lr) * 1024 + ls);
        const uint4* bs = (const uint4*)(Vb + (lr << 6) + ls);
        uint4* ad = (uint4*)(Asb[0] + lr * 72 + ls);
        uint4* bd = (uint4*)(Bsb[0] + lr * 72 + ls);
        ad[0] = as[0]; ad[1] = as[1];
        bd[0] = bs[0]; bd[1] = bs[1];
    }
    __syncthreads();

    int wm = (warp >> 1) * 16, wn = (warp & 1) * 32;
    int amr = lane & 15, akc = (lane >> 4) * 8;
    int btr = (lane & 7) + ((lane & 8) ? 8 : 0);
    int btc = (lane & 16) ? 8 : 0;

    float acc[4][4] = {};
    for (int ch = 0; ch < 16; ch++) {
        int buf = ch & 1;
        uint4 pa[2], pb[2];
        if (ch < 15) {
            int kn = (ch + 1) * 64;
            const uint4* as = (const uint4*)(U + (size_t)(q0 + lr) * 1024 + kn + ls);
            const uint4* bs = (const uint4*)(Vb + ((kn + lr) << 6) + ls);
            pa[0] = as[0]; pa[1] = as[1];
            pb[0] = bs[0]; pb[1] = bs[1];
        }
#pragma unroll
        for (int ks = 0; ks < 4; ks++) {
            int kk = ks * 16;
            uint32_t af[4], bf[2][4];
            ldm4(af, cvta_s(Asb[buf] + (wm + amr) * 72 + kk + akc));
#pragma unroll
            for (int np = 0; np < 2; np++)
                ldm4t(bf[np], cvta_s(Bsb[buf] + (kk + btr) * 72 + wn + np * 16 + btc));
#pragma unroll
            for (int ni = 0; ni < 4; ni++)
                mma16816(acc[ni], af, &bf[ni >> 1][(ni & 1) * 2]);
        }
        if (ch < 15) {
            int nb = buf ^ 1;
            uint4* ad = (uint4*)(Asb[nb] + lr * 72 + ls);
            uint4* bd = (uint4*)(Bsb[nb] + lr * 72 + ls);
            ad[0] = pa[0]; ad[1] = pa[1];
            bd[0] = pb[0]; bd[1] = pb[1];
        }
        __syncthreads();
    }

    int row = lane >> 2, colp = (lane & 3) * 2;
    int q = q0 + wm + row;
#pragma unroll
    for (int ni = 0; ni < 4; ni++) {
        int d = wn + ni * 8 + colp;
        __half* p = g_Oh + b * 1048576 + q * 1024 + v * 64 + d;
        *(__half2*)p = __floats2half2_rn(acc[ni][0] * UINV, acc[ni][1] * UINV);
        *(__half2*)(p + 8 * 1024) =
            __floats2half2_rn(acc[ni][2] * UINV, acc[ni][3] * UINV);
    }
}

// ================= K6: out[b,c,q] = inp + O @ Wo16, HMMA 64x128, KC=64 DB ==========
__global__ __launch_bounds__(256) void k6_out(const float* __restrict__ inp,
                                              float* __restrict__ out) {
    extern __shared__ __half sm6[];
    __half* Asb[2] = { sm6, sm6 + 64 * 72 };
    __half* Bsb[2] = { sm6 + 2 * 64 * 72, sm6 + 2 * 64 * 72 + 64 * 136 };
    float* Cs = (float*)sm6;
    int b = blockIdx.z;
    int c0 = blockIdx.x * 128, q0 = blockIdx.y * 64;
    const __half* Oq = g_Oh + b * 1048576;

    int t = threadIdx.x, lane = t & 31, w = t >> 5;
    int alr = t >> 2, als = (t & 3) * 16;
    int blr = t >> 2, bls = (t & 3) * 32;

    {
        const uint4* as = (const uint4*)(Oq + (q0 + alr) * 1024 + als);
        uint4* ad = (uint4*)(Asb[0] + alr * 72 + als);
        ad[0] = as[0]; ad[1] = as[1];
        const uint4* bs = (const uint4*)(g_Wo16 + blr * 512 + c0 + bls);
        uint4* bd = (uint4*)(Bsb[0] + blr * 136 + bls);
        bd[0] = bs[0]; bd[1] = bs[1]; bd[2] = bs[2]; bd[3] = bs[3];
    }
    __syncthreads();

    int wm = (w >> 2) * 32, wn = (w & 3) * 32;
    int amr = lane & 15, akc = (lane >> 4) * 8;
    int b_r = (lane & 7) + ((lane & 8) ? 8 : 0);
    int b_c = (lane & 16) ? 8 : 0;

    float acc[2][4][4] = {};
    for (int ch = 0; ch < 16; ch++) {
        int buf = ch & 1;
        uint4 pa[2], pb[4];
        if (ch < 15) {
            int kn = (ch + 1) * 64;
            const uint4* as = (const uint4*)(Oq + (q0 + alr) * 1024 + kn + als);
            pa[0] = as[0]; pa[1] = as[1];
            const uint4* bs = (const uint4*)(g_Wo16 + (kn + blr) * 512 + c0 + bls);
            pb[0] = bs[0]; pb[1] = bs[1]; pb[2] = bs[2]; pb[3] = bs[3];
        }
#pragma unroll
        for (int ks = 0; ks < 4; ks++) {
            int kk = ks * 16;
            uint32_t af[2][4], bf[2][4];
#pragma unroll
            for (int mi = 0; mi < 2; mi++)
                ldm4(af[mi], cvta_s(Asb[buf] + (wm + mi * 16 + amr) * 72 + kk + akc));
#pragma unroll
            for (int np = 0; np < 2; np++)
                ldm4t(bf[np], cvta_s(Bsb[buf] + (kk + b_r) * 136 + wn + np * 16 + b_c));
#pragma unroll
            for (int mi = 0; mi < 2; mi++)
#pragma unroll
                for (int ni = 0; ni < 4; ni++)
                    mma16816(acc[mi][ni], af[mi], &bf[ni >> 1][(ni & 1) * 2]);
        }
        if (ch < 15) {
            int nb = buf ^ 1;
            uint4* ad = (uint4*)(Asb[nb] + alr * 72 + als);
            ad[0] = pa[0]; ad[1] = pa[1];
            uint4* bd = (uint4*)(Bsb[nb] + blr * 136 + bls);
            bd[0] = pb[0]; bd[1] = pb[1]; bd[2] = pb[2]; bd[3] = pb[3];
        }
        __syncthreads();
    }

    int row = lane >> 2, cp = (lane & 3) * 2;
#pragma unroll
    for (int mi = 0; mi < 2; mi++)
#pragma unroll
        for (int ni = 0; ni < 4; ni++) {
            int qq = wm + mi * 16 + row;
            int cc2 = wn + ni * 8 + cp;
            Cs[cc2 * 68 + qq]           = acc[mi][ni][0];
            Cs[(cc2 + 1) * 68 + qq]     = acc[mi][ni][1];
            Cs[cc2 * 68 + qq + 8]       = acc[mi][ni][2];
            Cs[(cc2 + 1) * 68 + qq + 8] = acc[mi][ni][3];
        }
    __syncthreads();
#pragma unroll
    for (int i2 = 0; i2 < 8; i2++) {
        int idx = t + i2 * 256;
        int cc2 = idx >> 4, q4 = (idx & 15) * 4;
        size_t off = (size_t)b * 524288 + (size_t)(c0 + cc2) * 1024 + q0 + q4;
        float4 iv = *(const float4*)(inp + off);
        *(float4*)(out + off) = make_float4(iv.x + Cs[cc2 * 68 + q4],
                                            iv.y + Cs[cc2 * 68 + q4 + 1],
                                            iv.z + Cs[cc2 * 68 + q4 + 2],
                                            iv.w + Cs[cc2 * 68 + q4 + 3]);
    }
}

// ================= launch =================
extern "C" void kernel_launch(void* const* d_in, const int* in_sizes, int n_in,
                              void* d_out, int out_size) {
    const float* inp  = (const float*)d_in[0];
    const float* mask = (const float*)d_in[1];
    const float* Wq   = (const float*)d_in[2];
    const float* Wk   = (const float*)d_in[3];
    const float* Wv   = (const float*)d_in[4];
    const float* aq   = (const float*)d_in[5];
    const float* ak   = (const float*)d_in[6];
    const float* av   = (const float*)d_in[7];
    const float* Wl   = (const float*)d_in[8];
    const float* Ww   = (const float*)d_in[9];
    const float* Wo   = (const float*)d_in[10];
    float* out = (float*)d_out;

    const int SMEM_K34 = 16 * JST * 2;                        // 33024
    const int SMEM_K5  = 4 * 64 * 72 * 2;                     // 36864
    const int SMEM_K6  = (2 * 64 * 72 + 2 * 64 * 136) * 2;    // 53248
    cudaFuncSetAttribute(k34_softmax_U, cudaFuncAttributeMaxDynamicSharedMemorySize, SMEM_K34);
    cudaFuncSetAttribute(k5_O, cudaFuncAttributeMaxDynamicSharedMemorySize, SMEM_K5);
    cudaFuncSetAttribute(k6_out, cudaFuncAttributeMaxDynamicSharedMemorySize, SMEM_K6);

    kc0<<<3264, 256>>>(inp, Wq, Wk, Wv, aq, ak, av, Wo);
    k1_proj<<<dim3(8, 8, 6), 256>>>();
    k2_J<<<dim3(8, 8, 32), 256>>>();
    k34_softmax_U<<<dim3(1024, 2), 256, SMEM_K34>>>(mask, Wl, Ww);
    k5_O<<<dim3(16, 32), 256, SMEM_K5>>>();
    k6_out<<<dim3(4, 16, 2), 256, SMEM_K6>>>(inp, out);
}

// round 13
// speedup vs baseline: 1.0673x; 1.0154x over previous
#include <cuda_runtime.h>
#include <cuda_fp16.h>
#include <cstdint>

#define CIN 512
#define SEQ 1024

// ---------------- scratch ----------------
__device__ __half g_inp16[2 * 512 * 1024];           // [b][c][s]
__device__ __half g_W16[3 * 512 * 1024];             // [w][c][h*64+d] scale-folded
__device__ __half g_Wo16[1024 * 512];                // [j'=v*64+d][c] permuted fp16 Wo
__device__ __half g_Qh[2 * 16 * 1024 * 64];          // [b][h][s][d]
__device__ __half g_Kh[2 * 16 * 1024 * 64];          // [b][h][s][d]
__device__ __half g_Vh[2 * 16 * 1024 * 64];          // [b][h][k][d]
__device__ __half g_J[(size_t)2 * 16 * 1024 * 1024]; // [b][h][q][k] 64 MB
__device__ __half g_U[(size_t)2 * 16 * 1024 * 1024]; // [b][v][q][k] 64 MB (x256)
__device__ __half g_Oh[2 * 1024 * 1024];             // [b][q][v*64+d] fp16

#define USCALE 256.0f
#define UINV   (1.0f / 256.0f)

// ---------------- exp via MUFU ----------------
__device__ __forceinline__ float fast_exp(float x) {
    float r;
    asm("ex2.approx.f32 %0, %1;" : "=f"(r) : "f"(x * 1.4426950408889634f));
    return r;
}

// ---------------- mma helpers ----------------
__device__ __forceinline__ uint32_t cvta_s(const void* p) {
    return (uint32_t)__cvta_generic_to_shared(p);
}
__device__ __forceinline__ void ldm4(uint32_t* r, uint32_t a) {
    asm volatile("ldmatrix.sync.aligned.m8n8.x4.shared.b16 {%0,%1,%2,%3}, [%4];"
        : "=r"(r[0]), "=r"(r[1]), "=r"(r[2]), "=r"(r[3]) : "r"(a));
}
__device__ __forceinline__ void ldm4t(uint32_t* r, uint32_t a) {
    asm volatile("ldmatrix.sync.aligned.m8n8.x4.trans.shared.b16 {%0,%1,%2,%3}, [%4];"
        : "=r"(r[0]), "=r"(r[1]), "=r"(r[2]), "=r"(r[3]) : "r"(a));
}
__device__ __forceinline__ void mma16816(float* c, const uint32_t* a, const uint32_t* b) {
    asm volatile("mma.sync.aligned.m16n8k16.row.col.f32.f16.f16.f32 "
        "{%0,%1,%2,%3}, {%4,%5,%6,%7}, {%8,%9}, {%0,%1,%2,%3};"
        : "+f"(c[0]), "+f"(c[1]), "+f"(c[2]), "+f"(c[3])
        : "r"(a[0]), "r"(a[1]), "r"(a[2]), "r"(a[3]), "r"(b[0]), "r"(b[1]));
}

// ================= KC0: fp16 conversions + weight reorders =================
__global__ __launch_bounds__(256) void kc0(const float* __restrict__ inp,
        const float* __restrict__ Wq, const float* __restrict__ Wk,
        const float* __restrict__ Wv,
        const float* __restrict__ aq, const float* __restrict__ ak,
        const float* __restrict__ av, const float* __restrict__ Wo) {
    int bid = blockIdx.x, tid = threadIdx.x;
    if (bid < 2048) {
        int t = bid * 256 + tid;
        float2 v = *(const float2*)(inp + (size_t)t * 2);
        *(__half2*)(g_inp16 + (size_t)t * 2) = __floats2half2_rn(v.x, v.y);
        return;
    }
    if (bid < 2240) {
        __shared__ __half sT[8 * 1024];
        int u = bid - 2048;
        int w = u >> 6, r0 = (u & 63) * 8;
        const float* W = (w == 0) ? Wq : ((w == 1) ? Wk : Wv);
        float al = (w == 0) ? aq[0] : ((w == 1) ? ak[0] : av[0]);
        float sc = 1.0f / (1.0f + fast_exp(-al));
#pragma unroll
        for (int i = 0; i < 8; i++) {
            int idx = i * 256 + tid;
            int row = idx >> 8, col4 = (idx & 255) * 4;
            float4 v = *(const float4*)&W[(r0 + row) * 1024 + col4];
            __half* d = &sT[row * 1024 + col4];
            d[0] = __float2half_rn(v.x * sc);
            d[1] = __float2half_rn(v.y * sc);
            d[2] = __float2half_rn(v.z * sc);
            d[3] = __float2half_rn(v.w * sc);
        }
        __syncthreads();
#pragma unroll
        for (int i = 0; i < 4; i++) {
            int idx = i * 256 + tid;
            int row = idx >> 7, jo8 = (idx & 127) * 8;
            __half outv[8];
#pragma unroll
            for (int e = 0; e < 8; e++) {
                int jp = jo8 + e;
                outv[e] = sT[row * 1024 + (jp & 63) * 16 + (jp >> 6)];
            }
            *(uint4*)&g_W16[w * 524288 + (r0 + row) * 1024 + jo8] = *(uint4*)outv;
        }
        return;
    }
    {
        int u2 = (bid - 2240) * 256 + tid;
        int jp = u2 >> 8, cp = (u2 & 255) * 2;
        int wrow = ((jp & 63) << 4) | (jp >> 6);
        *(__half2*)(g_Wo16 + jp * 512 + cp) =
            __floats2half2_rn(Wo[wrow * 512 + cp], Wo[wrow * 512 + cp + 1]);
    }
}

// ================= K1: QKV projection, HMMA, 128x128, KC=32 DB, staged epilogue ====
__global__ __launch_bounds__(256) void k1_proj() {
    __shared__ __half s1[17408];
    __half* Asb[2] = { s1, s1 + 4352 };
    __half* Bsb[2] = { s1 + 8704, s1 + 13056 };
    int z = blockIdx.z;
    int b = z / 3, w = z % 3;
    int n0 = blockIdx.x * 128, m0 = blockIdx.y * 128;
    const __half* Ag = g_inp16 + b * 524288;
    const __half* Bg = g_W16 + w * 524288;

    int t = threadIdx.x, lane = t & 31, warp = t >> 5;
    int lrow = t >> 3, lcol = (t & 7) * 16;

    {
        const uint4* as = (const uint4*)(Ag + lrow * 1024 + m0 + lcol);
        const uint4* bs = (const uint4*)(Bg + lrow * 1024 + n0 + lcol);
        uint4* ad = (uint4*)(Asb[0] + lrow * 136 + lcol);
        uint4* bd = (uint4*)(Bsb[0] + lrow * 136 + lcol);
        ad[0] = as[0]; ad[1] = as[1];
        bd[0] = bs[0]; bd[1] = bs[1];
    }
    __syncthreads();

    int wm = (warp >> 2) * 64, wn = (warp & 3) * 32;
    int a_r = (lane & 7) + ((lane & 16) ? 8 : 0);
    int a_c = (lane & 8) ? 8 : 0;
    int b_r = (lane & 7) + ((lane & 8) ? 8 : 0);
    int b_c = (lane & 16) ? 8 : 0;

    float acc[4][4][4] = {};
    for (int ch = 0; ch < 16; ch++) {
        int buf = ch & 1;
        uint4 pa0, pa1, pb0, pb1;
        if (ch < 15) {
            const uint4* as = (const uint4*)(Ag + ((ch + 1) * 32 + lrow) * 1024 + m0 + lcol);
            const uint4* bs = (const uint4*)(Bg + ((ch + 1) * 32 + lrow) * 1024 + n0 + lcol);
            pa0 = as[0]; pa1 = as[1];
            pb0 = bs[0]; pb1 = bs[1];
        }
#pragma unroll
        for (int ks = 0; ks < 2; ks++) {
            int kk = ks * 16;
            uint32_t af[4][4], bf[2][4];
#pragma unroll
            for (int mi = 0; mi < 4; mi++)
                ldm4t(af[mi], cvta_s(Asb[buf] + (kk + a_r) * 136 + wm + mi * 16 + a_c));
#pragma unroll
            for (int np = 0; np < 2; np++)
                ldm4t(bf[np], cvta_s(Bsb[buf] + (kk + b_r) * 136 + wn + np * 16 + b_c));
#pragma unroll
            for (int mi = 0; mi < 4; mi++)
#pragma unroll
                for (int ni = 0; ni < 4; ni++)
                    mma16816(acc[mi][ni], af[mi], &bf[ni >> 1][(ni & 1) * 2]);
        }
        if (ch < 15) {
            int nb = buf ^ 1;
            uint4* ad = (uint4*)(Asb[nb] + lrow * 136 + lcol);
            uint4* bd = (uint4*)(Bsb[nb] + lrow * 136 + lcol);
            ad[0] = pa0; ad[1] = pa1;
            bd[0] = pb0; bd[1] = pb1;
        }
        __syncthreads();
    }

    __half* stage = s1;
    int row = lane >> 2, colp = (lane & 3) * 2;
#pragma unroll
    for (int mi = 0; mi < 4; mi++)
#pragma unroll
        for (int ni = 0; ni < 4; ni++) {
            int rr = wm + mi * 16 + row, cc = wn + ni * 8 + colp;
            *(__half2*)&stage[rr * 136 + cc] =
                __floats2half2_rn(acc[mi][ni][0], acc[mi][ni][1]);
            *(__half2*)&stage[(rr + 8) * 136 + cc] =
                __floats2half2_rn(acc[mi][ni][2], acc[mi][ni][3]);
        }
    __syncthreads();

    __half* base = (w == 0) ? g_Qh : ((w == 1) ? g_Kh : g_Vh);
#pragma unroll
    for (int i = 0; i < 8; i++) {
        int idx = i * 256 + t;
        int rr = idx >> 4, chunk = idx & 15;
        int jp = n0 + chunk * 8;
        int h = jp >> 6, d = jp & 63;
        *(uint4*)(base + (((b * 16 + h) * 1024 + m0 + rr) << 6) + d) =
            *(const uint4*)&stage[rr * 136 + chunk * 8];
    }
}

// ================= K2: J = Q.K^T per (b,h), HMMA, K=64 single-shot, staged epilogue =
__global__ __launch_bounds__(256) void k2_J() {
    __shared__ __half s2[18432];
    __half* As = s2;
    __half* Bs = s2 + 9216;
    int bh = blockIdx.z;
    int q0 = blockIdx.y * 128, k0 = blockIdx.x * 128;
    const __half* Qb = g_Qh + ((size_t)bh << 16);
    const __half* Kb = g_Kh + ((size_t)bh << 16);

    int t = threadIdx.x, lane = t & 31, warp = t >> 5;
    {
        int lr = t >> 1, ls = (t & 1) * 32;
        const uint4* qs = (const uint4*)(Qb + ((q0 + lr) << 6) + ls);
        const uint4* ks = (const uint4*)(Kb + ((k0 + lr) << 6) + ls);
        uint4* ad = (uint4*)(As + lr * 72 + ls);
        uint4* bd = (uint4*)(Bs + lr * 72 + ls);
#pragma unroll
        for (int i = 0; i < 4; i++) { ad[i] = qs[i]; bd[i] = ks[i]; }
    }
    __syncthreads();

    int wm = (warp >> 2) * 64, wn = (warp & 3) * 32;
    int amr = lane & 15, akc = (lane >> 4) * 8;
    int bnr = (lane & 7) + ((lane & 16) ? 8 : 0);
    int bkc = (lane & 8) ? 8 : 0;

    float acc[4][4][4] = {};
#pragma unroll
    for (int ks = 0; ks < 4; ks++) {
        int kk = ks * 16;
        uint32_t af[4][4], bf[2][4];
#pragma unroll
        for (int mi = 0; mi < 4; mi++)
            ldm4(af[mi], cvta_s(As + (wm + mi * 16 + amr) * 72 + kk + akc));
#pragma unroll
        for (int np = 0; np < 2; np++)
            ldm4(bf[np], cvta_s(Bs + (wn + np * 16 + bnr) * 72 + kk + bkc));
#pragma unroll
        for (int mi = 0; mi < 4; mi++)
#pragma unroll
            for (int ni = 0; ni < 4; ni++)
                mma16816(acc[mi][ni], af[mi], &bf[ni >> 1][(ni & 1) * 2]);
    }
    __syncthreads();

    __half* stage = s2;
    int row = lane >> 2, colp = (lane & 3) * 2;
#pragma unroll
    for (int mi = 0; mi < 4; mi++)
#pragma unroll
        for (int ni = 0; ni < 4; ni++) {
            int rr = wm + mi * 16 + row, cc = wn + ni * 8 + colp;
            *(__half2*)&stage[rr * 136 + cc] =
                __floats2half2_rn(acc[mi][ni][0], acc[mi][ni][1]);
            *(__half2*)&stage[(rr + 8) * 136 + cc] =
                __floats2half2_rn(acc[mi][ni][2], acc[mi][ni][3]);
        }
    __syncthreads();

    __half* Jp = g_J + ((size_t)bh << 20);
#pragma unroll
    for (int i = 0; i < 8; i++) {
        int idx = i * 256 + t;
        int rr = idx >> 4, chunk = idx & 15;
        *(uint4*)&Jp[(size_t)(q0 + rr) * 1024 + k0 + chunk * 8] =
            *(const uint4*)&stage[rr * 136 + chunk * 8];
    }
}

// ====== K34: per (b,q): EL = J@Wl - mask, softmax over k, U = W@Ww — all HMMA ======
#define JST 1032
__global__ __launch_bounds__(256) void k34_softmax_U(const float* __restrict__ mask,
                                                     const float* __restrict__ Wl,
                                                     const float* __restrict__ Ww) {
    extern __shared__ __half sJ[];
    __shared__ __half sWl[16 * 24];
    __shared__ __half sWwS[16 * 24];
    __shared__ float sMask[1024];
    __shared__ float red[8][16];
    __shared__ float sInv[16];

    int q = blockIdx.x, b = blockIdx.y;
    int tid = threadIdx.x, lane = tid & 31, w = tid >> 5;
    const __half* Jb = g_J + (size_t)b * 16777216 + (size_t)q * 1024;

    { int h = tid >> 4, g = tid & 15; sWl[h * 24 + g] = __float2half(Wl[h * 16 + g]); }
    { float4 m4 = *(const float4*)(mask + b * 1024 + tid * 4);
      *(float4*)&sMask[tid * 4] = m4; }
#pragma unroll
    for (int p = 0; p < 2; p++) {
        int h = w * 2 + p;
        const uint4* src = (const uint4*)(Jb + (size_t)h * 1048576);
#pragma unroll
        for (int it = 0; it < 4; it++)
            *(uint4*)&sJ[h * JST + (lane + it * 32) * 8] = src[lane + it * 32];
    }
    __syncthreads();

    // ---- phase 1 ----
    uint32_t bWl[4];
    {
        int b_r = (lane & 7) + ((lane & 8) ? 8 : 0);
        int b_c = (lane & 16) ? 8 : 0;
        ldm4t(bWl, cvta_s(sWl + b_r * 24 + b_c));
    }
    int a_r = (lane & 7) + ((lane & 16) ? 8 : 0);
    int a_c = (lane & 8) ? 8 : 0;
    int r = lane >> 2, cg = (lane & 3) * 2;
    int kbase = w * 128;
    float psum4[4] = {};
#pragma unroll
    for (int i = 0; i < 8; i++) {
        int kcol = kbase + i * 16;
        uint32_t af[4];
        ldm4t(af, cvta_s(sJ + a_r * JST + kcol + a_c));
        float c0[4] = {}, c1[4] = {};
        mma16816(c0, af, &bWl[0]);
        mma16816(c1, af, &bWl[2]);
        float mk0 = sMask[kcol + r], mk1 = sMask[kcol + r + 8];
        float e00 = fast_exp(c0[0] - mk0), e01 = fast_exp(c0[1] - mk0);
        float e02 = fast_exp(c0[2] - mk1), e03 = fast_exp(c0[3] - mk1);
        float e10 = fast_exp(c1[0] - mk0), e11 = fast_exp(c1[1] - mk0);
        float e12 = fast_exp(c1[2] - mk1), e13 = fast_exp(c1[3] - mk1);
        psum4[0] += e00 + e02; psum4[1] += e01 + e03;
        psum4[2] += e10 + e12; psum4[3] += e11 + e13;
        *(__half2*)&sJ[r * JST + kcol + cg]           = __floats2half2_rn(e00, e01);
        *(__half2*)&sJ[(r + 8) * JST + kcol + cg]     = __floats2half2_rn(e02, e03);
        *(__half2*)&sJ[r * JST + kcol + 8 + cg]       = __floats2half2_rn(e10, e11);
        *(__half2*)&sJ[(r + 8) * JST + kcol + 8 + cg] = __floats2half2_rn(e12, e13);
    }
#pragma unroll
    for (int s = 16; s >= 4; s >>= 1) {
#pragma unroll
        for (int j = 0; j < 4; j++)
            psum4[j] += __shfl_xor_sync(0xffffffffu, psum4[j], s);
    }
    if (lane < 4) {
        red[w][2 * lane]     = psum4[0];
        red[w][2 * lane + 1] = psum4[1];
        red[w][2 * lane + 8] = psum4[2];
        red[w][2 * lane + 9] = psum4[3];
    }
    __syncthreads();
    if (tid < 16) {
        float s = 0.f;
#pragma unroll
        for (int ww = 0; ww < 8; ww++) s += red[ww][tid];
        sInv[tid] = USCALE / s;
    }
    __syncthreads();
    { int v = tid >> 4, g = tid & 15;
      sWwS[v * 24 + g] = __float2half(sInv[g] * Ww[g * 16 + v]); }
    __syncthreads();

    // ---- phase 2 ----
    uint32_t aW[4];
    { int amr = lane & 15, akc2 = (lane >> 4) * 8;
      ldm4(aW, cvta_s(sWwS + amr * 24 + akc2)); }
    int bnr = (lane & 7) + ((lane & 16) ? 8 : 0);
    int bkc = (lane & 8) ? 8 : 0;
#pragma unroll
    for (int i = 0; i < 8; i++) {
        int kcol = kbase + i * 16;
        uint32_t bf[4];
        ldm4(bf, cvta_s(sJ + bnr * JST + kcol + bkc));
        float c0[4] = {}, c1[4] = {};
        mma16816(c0, aW, &bf[0]);
        mma16816(c1, aW, &bf[2]);
        __syncwarp();
        *(__half2*)&sJ[r * JST + kcol + cg]           = __floats2half2_rn(c0[0], c0[1]);
        *(__half2*)&sJ[(r + 8) * JST + kcol + cg]     = __floats2half2_rn(c0[2], c0[3]);
        *(__half2*)&sJ[r * JST + kcol + 8 + cg]       = __floats2half2_rn(c1[0], c1[1]);
        *(__half2*)&sJ[(r + 8) * JST + kcol + 8 + cg] = __floats2half2_rn(c1[2], c1[3]);
    }
    __syncwarp();
    __half* Ub = g_U + (size_t)b * 16777216 + (size_t)q * 1024;
#pragma unroll
    for (int it = 0; it < 8; it++) {
        int idx = lane + it * 32;
        int v = idx >> 4, uu = (idx & 15) * 8;
        *(uint4*)&Ub[(size_t)v * 1048576 + kbase + uu] =
            *(const uint4*)&sJ[v * JST + kbase + uu];
    }
}

// ================= K5: O = U.V per (b,v), HMMA, 128x64, KC=64 DB, fp16 out =========
__global__ __launch_bounds__(256) void k5_O() {
    extern __shared__ __half sm5[];
    __half* Asb[2] = { sm5, sm5 + 128 * 72 };
    __half* Bsb[2] = { sm5 + 2 * 128 * 72, sm5 + 2 * 128 * 72 + 64 * 72 };
    int bv = blockIdx.y;
    int b = bv >> 4, v = bv & 15;
    int q0 = blockIdx.x * 128;
    const __half* U  = g_U + ((size_t)bv << 20);
    const __half* Vb = g_Vh + ((size_t)bv << 16);

    int t = threadIdx.x, lane = t & 31, warp = t >> 5;
    int alr = t >> 1, als = (t & 1) * 32;
    int blr = t >> 2, bls = (t & 3) * 16;

    {
        const uint4* as = (const uint4*)(U + (size_t)(q0 + alr) * 1024 + als);
        const uint4* bs = (const uint4*)(Vb + (blr << 6) + bls);
        uint4* ad = (uint4*)(Asb[0] + alr * 72 + als);
        uint4* bd = (uint4*)(Bsb[0] + blr * 72 + bls);
#pragma unroll
        for (int i = 0; i < 4; i++) ad[i] = as[i];
        bd[0] = bs[0]; bd[1] = bs[1];
    }
    __syncthreads();

    int wm = (warp >> 1) * 32, wn = (warp & 1) * 32;
    int amr = lane & 15, akc = (lane >> 4) * 8;
    int btr = (lane & 7) + ((lane & 8) ? 8 : 0);
    int btc = (lane & 16) ? 8 : 0;

    float acc[2][4][4] = {};
    for (int ch = 0; ch < 16; ch++) {
        int buf = ch & 1;
        uint4 pa[4], pb[2];
        if (ch < 15) {
            int kn = (ch + 1) * 64;
            const uint4* as = (const uint4*)(U + (size_t)(q0 + alr) * 1024 + kn + als);
            const uint4* bs = (const uint4*)(Vb + ((kn + blr) << 6) + bls);
#pragma unroll
            for (int i = 0; i < 4; i++) pa[i] = as[i];
            pb[0] = bs[0]; pb[1] = bs[1];
        }
#pragma unroll
        for (int ks = 0; ks < 4; ks++) {
            int kk = ks * 16;
            uint32_t af[2][4], bf[2][4];
#pragma unroll
            for (int mi = 0; mi < 2; mi++)
                ldm4(af[mi], cvta_s(Asb[buf] + (wm + mi * 16 + amr) * 72 + kk + akc));
#pragma unroll
            for (int np = 0; np < 2; np++)
                ldm4t(bf[np], cvta_s(Bsb[buf] + (kk + btr) * 72 + wn + np * 16 + btc));
#pragma unroll
            for (int mi = 0; mi < 2; mi++)
#pragma unroll
                for (int ni = 0; ni < 4; ni++)
                    mma16816(acc[mi][ni], af[mi], &bf[ni >> 1][(ni & 1) * 2]);
        }
        if (ch < 15) {
            int nb = buf ^ 1;
            uint4* ad = (uint4*)(Asb[nb] + alr * 72 + als);
            uint4* bd = (uint4*)(Bsb[nb] + blr * 72 + bls);
#pragma unroll
            for (int i = 0; i < 4; i++) ad[i] = pa[i];
            bd[0] = pb[0]; bd[1] = pb[1];
        }
        __syncthreads();
    }

    int row = lane >> 2, colp = (lane & 3) * 2;
#pragma unroll
    for (int mi = 0; mi < 2; mi++) {
        int q = q0 + wm + mi * 16 + row;
#pragma unroll
        for (int ni = 0; ni < 4; ni++) {
            int d = wn + ni * 8 + colp;
            __half* p = g_Oh + b * 1048576 + q * 1024 + v * 64 + d;
            *(__half2*)p = __floats2half2_rn(acc[mi][ni][0] * UINV, acc[mi][ni][1] * UINV);
            *(__half2*)(p + 8 * 1024) =
                __floats2half2_rn(acc[mi][ni][2] * UINV, acc[mi][ni][3] * UINV);
        }
    }
}

// ================= K6: out[b,c,q] = inp + O @ Wo16, HMMA 64q x 64c, KC=64 DB =======
// 64-wide c tiles: grid (8,16,2)=256 blocks (vs 128 sub-wave before), smem 36 KB.
__global__ __launch_bounds__(256) void k6_out(const float* __restrict__ inp,
                                              float* __restrict__ out) {
    extern __shared__ __half sm6[];
    __half* Asb[2] = { sm6, sm6 + 64 * 72 };
    __half* Bsb[2] = { sm6 + 2 * 64 * 72, sm6 + 2 * 64 * 72 + 64 * 72 };
    float* Cs = (float*)sm6;
    int b = blockIdx.z;
    int c0 = blockIdx.x * 64, q0 = blockIdx.y * 64;
    const __half* Oq = g_Oh + b * 1048576;

    int t = threadIdx.x, lane = t & 31, w = t >> 5;
    int lr = t >> 2, ls = (t & 3) * 16;   // both loaders: row 0..63, 2 uint4 each

    {
        const uint4* as = (const uint4*)(Oq + (q0 + lr) * 1024 + ls);
        uint4* ad = (uint4*)(Asb[0] + lr * 72 + ls);
        ad[0] = as[0]; ad[1] = as[1];
        const uint4* bs = (const uint4*)(g_Wo16 + lr * 512 + c0 + ls);
        uint4* bd = (uint4*)(Bsb[0] + lr * 72 + ls);
        bd[0] = bs[0]; bd[1] = bs[1];
    }
    __syncthreads();

    int wm = (w >> 2) * 32, wn = (w & 3) * 16;
    int amr = lane & 15, akc = (lane >> 4) * 8;
    int b_r = (lane & 7) + ((lane & 8) ? 8 : 0);
    int b_c = (lane & 16) ? 8 : 0;

    float acc[2][2][4] = {};
    for (int ch = 0; ch < 16; ch++) {
        int buf = ch & 1;
        uint4 pa[2], pb[2];
        if (ch < 15) {
            int kn = (ch + 1) * 64;
            const uint4* as = (const uint4*)(Oq + (q0 + lr) * 1024 + kn + ls);
            pa[0] = as[0]; pa[1] = as[1];
            const uint4* bs = (const uint4*)(g_Wo16 + (kn + lr) * 512 + c0 + ls);
            pb[0] = bs[0]; pb[1] = bs[1];
        }
#pragma unroll
        for (int ks = 0; ks < 4; ks++) {
            int kk = ks * 16;
            uint32_t af[2][4], bf[4];
#pragma unroll
            for (int mi = 0; mi < 2; mi++)
                ldm4(af[mi], cvta_s(Asb[buf] + (wm + mi * 16 + amr) * 72 + kk + akc));
            ldm4t(bf, cvta_s(Bsb[buf] + (kk + b_r) * 72 + wn + b_c));
#pragma unroll
            for (int mi = 0; mi < 2; mi++)
#pragma unroll
                for (int ni = 0; ni < 2; ni++)
                    mma16816(acc[mi][ni], af[mi], &bf[ni * 2]);
        }
        if (ch < 15) {
            int nb = buf ^ 1;
            uint4* ad = (uint4*)(Asb[nb] + lr * 72 + ls);
            ad[0] = pa[0]; ad[1] = pa[1];
            uint4* bd = (uint4*)(Bsb[nb] + lr * 72 + ls);
            bd[0] = pb[0]; bd[1] = pb[1];
        }
        __syncthreads();
    }

    int row = lane >> 2, cp = (lane & 3) * 2;
#pragma unroll
    for (int mi = 0; mi < 2; mi++)
#pragma unroll
        for (int ni = 0; ni < 2; ni++) {
            int qq = wm + mi * 16 + row;
            int cc2 = wn + ni * 8 + cp;
            Cs[cc2 * 68 + qq]           = acc[mi][ni][0];
            Cs[(cc2 + 1) * 68 + qq]     = acc[mi][ni][1];
            Cs[cc2 * 68 + qq + 8]       = acc[mi][ni][2];
            Cs[(cc2 + 1) * 68 + qq + 8] = acc[mi][ni][3];
        }
    __syncthreads();
#pragma unroll
    for (int i2 = 0; i2 < 4; i2++) {
        int idx = t + i2 * 256;              // 0..1023 : 64c x 16 float4
        int cc2 = idx >> 4, q4 = (idx & 15) * 4;
        size_t off = (size_t)b * 524288 + (size_t)(c0 + cc2) * 1024 + q0 + q4;
        float4 iv = *(const float4*)(inp + off);
        *(float4*)(out + off) = make_float4(iv.x + Cs[cc2 * 68 + q4],
                                            iv.y + Cs[cc2 * 68 + q4 + 1],
                                            iv.z + Cs[cc2 * 68 + q4 + 2],
                                            iv.w + Cs[cc2 * 68 + q4 + 3]);
    }
}

// ================= launch =================
extern "C" void kernel_launch(void* const* d_in, const int* in_sizes, int n_in,
                              void* d_out, int out_size) {
    const float* inp  = (const float*)d_in[0];
    const float* mask = (const float*)d_in[1];
    const float* Wq   = (const float*)d_in[2];
    const float* Wk   = (const float*)d_in[3];
    const float* Wv   = (const float*)d_in[4];
    const float* aq   = (const float*)d_in[5];
    const float* ak   = (const float*)d_in[6];
    const float* av   = (const float*)d_in[7];
    const float* Wl   = (const float*)d_in[8];
    const float* Ww   = (const float*)d_in[9];
    const float* Wo   = (const float*)d_in[10];
    float* out = (float*)d_out;

    const int SMEM_K34 = 16 * JST * 2;                        // 33024
    const int SMEM_K5  = (2 * 128 * 72 + 2 * 64 * 72) * 2;    // 55296
    const int SMEM_K6  = 4 * 64 * 72 * 2;                     // 36864
    cudaFuncSetAttribute(k34_softmax_U, cudaFuncAttributeMaxDynamicSharedMemorySize, SMEM_K34);
    cudaFuncSetAttribute(k5_O, cudaFuncAttributeMaxDynamicSharedMemorySize, SMEM_K5);
    cudaFuncSetAttribute(k6_out, cudaFuncAttributeMaxDynamicSharedMemorySize, SMEM_K6);

    kc0<<<3264, 256>>>(inp, Wq, Wk, Wv, aq, ak, av, Wo);
    k1_proj<<<dim3(8, 8, 6), 256>>>();
    k2_J<<<dim3(8, 8, 32), 256>>>();
    k34_softmax_U<<<dim3(1024, 2), 256, SMEM_K34>>>(mask, Wl, Ww);
    k5_O<<<dim3(8, 32), 256, SMEM_K5>>>();
    k6_out<<<dim3(8, 16, 2), 256, SMEM_K6>>>(inp, out);
}

// round 14
// speedup vs baseline: 1.1112x; 1.0412x over previous
#include <cuda_runtime.h>
#include <cuda_fp16.h>
#include <cstdint>

#define CIN 512
#define SEQ 1024

// ---------------- scratch ----------------
__device__ __half  g_inp16[2 * 512 * 1024];            // [b][c][s]
__device__ __half  g_W16[3 * 512 * 1024];              // [w][c][h*64+d] scale-folded
__device__ __half  g_Wo16[1024 * 512];                 // [j'=v*64+d][c]
__device__ __half  g_Qh[2 * 16 * 1024 * 64];           // [b][h][s][d]
__device__ __half  g_Kh[2 * 16 * 1024 * 64];           // [b][h][s][d]
__device__ __half  g_Vh[2 * 16 * 1024 * 64];           // [b][h][k][d]
__device__ uint8_t g_J[(size_t)2 * 16 * 1024 * 1024];  // [b][h][q][k] e4m3, 32 MB
__device__ uint8_t g_U[(size_t)2 * 16 * 1024 * 1024];  // [b][v][q][k] e4m3 (x65536), 32 MB
__device__ __half  g_Oh[2 * 1024 * 1024];              // [b][q][v*64+d] fp16

#define USCALE 65536.0f
#define UINV   (1.0f / 65536.0f)

// ---------------- exp via MUFU ----------------
__device__ __forceinline__ float fast_exp(float x) {
    float r;
    asm("ex2.approx.f32 %0, %1;" : "=f"(r) : "f"(x * 1.4426950408889634f));
    return r;
}

// ---------------- fp8 converts (HW cvt, sm_89+) ----------------
__device__ __forceinline__ uint16_t h2_to_e4m3x2(uint32_t h2) {
    uint16_t r;
    asm("cvt.rn.satfinite.e4m3x2.f16x2 %0, %1;" : "=h"(r) : "r"(h2));
    return r;
}
__device__ __forceinline__ uint32_t e4m3x2_to_h2(uint16_t u) {
    uint32_t r;
    asm("cvt.rn.f16x2.e4m3x2 %0, %1;" : "=r"(r) : "h"(u));
    return r;
}
// 16 fp8 (one uint4) -> 16 halves (two uint4)
__device__ __forceinline__ void f8x16_to_h16(uint4 raw, uint4* o) {
    uint16_t* pr = (uint16_t*)&raw;
    uint32_t hh[8];
#pragma unroll
    for (int e = 0; e < 8; e++) hh[e] = e4m3x2_to_h2(pr[e]);
    o[0] = *(uint4*)&hh[0];
    o[1] = *(uint4*)&hh[4];
}
// 16 halves (8 packed half2) -> 16 fp8 (one uint4)
__device__ __forceinline__ uint4 h16_to_f8x16(const uint32_t* hsrc) {
    uint16_t e[8];
#pragma unroll
    for (int p = 0; p < 8; p++) e[p] = h2_to_e4m3x2(hsrc[p]);
    return *(uint4*)e;
}

// ---------------- mma helpers ----------------
__device__ __forceinline__ uint32_t cvta_s(const void* p) {
    return (uint32_t)__cvta_generic_to_shared(p);
}
__device__ __forceinline__ void ldm4(uint32_t* r, uint32_t a) {
    asm volatile("ldmatrix.sync.aligned.m8n8.x4.shared.b16 {%0,%1,%2,%3}, [%4];"
        : "=r"(r[0]), "=r"(r[1]), "=r"(r[2]), "=r"(r[3]) : "r"(a));
}
__device__ __forceinline__ void ldm4t(uint32_t* r, uint32_t a) {
    asm volatile("ldmatrix.sync.aligned.m8n8.x4.trans.shared.b16 {%0,%1,%2,%3}, [%4];"
        : "=r"(r[0]), "=r"(r[1]), "=r"(r[2]), "=r"(r[3]) : "r"(a));
}
__device__ __forceinline__ void mma16816(float* c, const uint32_t* a, const uint32_t* b) {
    asm volatile("mma.sync.aligned.m16n8k16.row.col.f32.f16.f16.f32 "
        "{%0,%1,%2,%3}, {%4,%5,%6,%7}, {%8,%9}, {%0,%1,%2,%3};"
        : "+f"(c[0]), "+f"(c[1]), "+f"(c[2]), "+f"(c[3])
        : "r"(a[0]), "r"(a[1]), "r"(a[2]), "r"(a[3]), "r"(b[0]), "r"(b[1]));
}

// ================= KC0: fp16 conversions + weight reorders =================
__global__ __launch_bounds__(256) void kc0(const float* __restrict__ inp,
        const float* __restrict__ Wq, const float* __restrict__ Wk,
        const float* __restrict__ Wv,
        const float* __restrict__ aq, const float* __restrict__ ak,
        const float* __restrict__ av, const float* __restrict__ Wo) {
    int bid = blockIdx.x, tid = threadIdx.x;
    if (bid < 2048) {
        int t = bid * 256 + tid;
        float2 v = *(const float2*)(inp + (size_t)t * 2);
        *(__half2*)(g_inp16 + (size_t)t * 2) = __floats2half2_rn(v.x, v.y);
        return;
    }
    if (bid < 2240) {
        __shared__ __half sT[8 * 1024];
        int u = bid - 2048;
        int w = u >> 6, r0 = (u & 63) * 8;
        const float* W = (w == 0) ? Wq : ((w == 1) ? Wk : Wv);
        float al = (w == 0) ? aq[0] : ((w == 1) ? ak[0] : av[0]);
        float sc = 1.0f / (1.0f + fast_exp(-al));
#pragma unroll
        for (int i = 0; i < 8; i++) {
            int idx = i * 256 + tid;
            int row = idx >> 8, col4 = (idx & 255) * 4;
            float4 v = *(const float4*)&W[(r0 + row) * 1024 + col4];
            __half* d = &sT[row * 1024 + col4];
            d[0] = __float2half_rn(v.x * sc);
            d[1] = __float2half_rn(v.y * sc);
            d[2] = __float2half_rn(v.z * sc);
            d[3] = __float2half_rn(v.w * sc);
        }
        __syncthreads();
#pragma unroll
        for (int i = 0; i < 4; i++) {
            int idx = i * 256 + tid;
            int row = idx >> 7, jo8 = (idx & 127) * 8;
            __half outv[8];
#pragma unroll
            for (int e = 0; e < 8; e++) {
                int jp = jo8 + e;
                outv[e] = sT[row * 1024 + (jp & 63) * 16 + (jp >> 6)];
            }
            *(uint4*)&g_W16[w * 524288 + (r0 + row) * 1024 + jo8] = *(uint4*)outv;
        }
        return;
    }
    {
        int u2 = (bid - 2240) * 256 + tid;
        int jp = u2 >> 8, cp = (u2 & 255) * 2;
        int wrow = ((jp & 63) << 4) | (jp >> 6);
        *(__half2*)(g_Wo16 + jp * 512 + cp) =
            __floats2half2_rn(Wo[wrow * 512 + cp], Wo[wrow * 512 + cp + 1]);
    }
}

// ================= K1: QKV projection, HMMA, 128x128, KC=32 DB, staged epilogue ====
__global__ __launch_bounds__(256) void k1_proj() {
    __shared__ __half s1[17408];
    __half* Asb[2] = { s1, s1 + 4352 };
    __half* Bsb[2] = { s1 + 8704, s1 + 13056 };
    int z = blockIdx.z;
    int b = z / 3, w = z % 3;
    int n0 = blockIdx.x * 128, m0 = blockIdx.y * 128;
    const __half* Ag = g_inp16 + b * 524288;
    const __half* Bg = g_W16 + w * 524288;

    int t = threadIdx.x, lane = t & 31, warp = t >> 5;
    int lrow = t >> 3, lcol = (t & 7) * 16;

    {
        const uint4* as = (const uint4*)(Ag + lrow * 1024 + m0 + lcol);
        const uint4* bs = (const uint4*)(Bg + lrow * 1024 + n0 + lcol);
        uint4* ad = (uint4*)(Asb[0] + lrow * 136 + lcol);
        uint4* bd = (uint4*)(Bsb[0] + lrow * 136 + lcol);
        ad[0] = as[0]; ad[1] = as[1];
        bd[0] = bs[0]; bd[1] = bs[1];
    }
    __syncthreads();

    int wm = (warp >> 2) * 64, wn = (warp & 3) * 32;
    int a_r = (lane & 7) + ((lane & 16) ? 8 : 0);
    int a_c = (lane & 8) ? 8 : 0;
    int b_r = (lane & 7) + ((lane & 8) ? 8 : 0);
    int b_c = (lane & 16) ? 8 : 0;

    float acc[4][4][4] = {};
    for (int ch = 0; ch < 16; ch++) {
        int buf = ch & 1;
        uint4 pa0, pa1, pb0, pb1;
        if (ch < 15) {
            const uint4* as = (const uint4*)(Ag + ((ch + 1) * 32 + lrow) * 1024 + m0 + lcol);
            const uint4* bs = (const uint4*)(Bg + ((ch + 1) * 32 + lrow) * 1024 + n0 + lcol);
            pa0 = as[0]; pa1 = as[1];
            pb0 = bs[0]; pb1 = bs[1];
        }
#pragma unroll
        for (int ks = 0; ks < 2; ks++) {
            int kk = ks * 16;
            uint32_t af[4][4], bf[2][4];
#pragma unroll
            for (int mi = 0; mi < 4; mi++)
                ldm4t(af[mi], cvta_s(Asb[buf] + (kk + a_r) * 136 + wm + mi * 16 + a_c));
#pragma unroll
            for (int np = 0; np < 2; np++)
                ldm4t(bf[np], cvta_s(Bsb[buf] + (kk + b_r) * 136 + wn + np * 16 + b_c));
#pragma unroll
            for (int mi = 0; mi < 4; mi++)
#pragma unroll
                for (int ni = 0; ni < 4; ni++)
                    mma16816(acc[mi][ni], af[mi], &bf[ni >> 1][(ni & 1) * 2]);
        }
        if (ch < 15) {
            int nb = buf ^ 1;
            uint4* ad = (uint4*)(Asb[nb] + lrow * 136 + lcol);
            uint4* bd = (uint4*)(Bsb[nb] + lrow * 136 + lcol);
            ad[0] = pa0; ad[1] = pa1;
            bd[0] = pb0; bd[1] = pb1;
        }
        __syncthreads();
    }

    __half* stage = s1;
    int row = lane >> 2, colp = (lane & 3) * 2;
#pragma unroll
    for (int mi = 0; mi < 4; mi++)
#pragma unroll
        for (int ni = 0; ni < 4; ni++) {
            int rr = wm + mi * 16 + row, cc = wn + ni * 8 + colp;
            *(__half2*)&stage[rr * 136 + cc] =
                __floats2half2_rn(acc[mi][ni][0], acc[mi][ni][1]);
            *(__half2*)&stage[(rr + 8) * 136 + cc] =
                __floats2half2_rn(acc[mi][ni][2], acc[mi][ni][3]);
        }
    __syncthreads();

    __half* base = (w == 0) ? g_Qh : ((w == 1) ? g_Kh : g_Vh);
#pragma unroll
    for (int i = 0; i < 8; i++) {
        int idx = i * 256 + t;
        int rr = idx >> 4, chunk = idx & 15;
        int jp = n0 + chunk * 8;
        int h = jp >> 6, d = jp & 63;
        *(uint4*)(base + (((b * 16 + h) * 1024 + m0 + rr) << 6) + d) =
            *(const uint4*)&stage[rr * 136 + chunk * 8];
    }
}

// ================= K2: J = Q.K^T per (b,h), HMMA, staged epilogue, fp8 J out =======
__global__ __launch_bounds__(256) void k2_J() {
    __shared__ __half s2[18432];
    __half* As = s2;
    __half* Bs = s2 + 9216;
    int bh = blockIdx.z;
    int q0 = blockIdx.y * 128, k0 = blockIdx.x * 128;
    const __half* Qb = g_Qh + ((size_t)bh << 16);
    const __half* Kb = g_Kh + ((size_t)bh << 16);

    int t = threadIdx.x, lane = t & 31, warp = t >> 5;
    {
        int lr = t >> 1, ls = (t & 1) * 32;
        const uint4* qs = (const uint4*)(Qb + ((q0 + lr) << 6) + ls);
        const uint4* ks = (const uint4*)(Kb + ((k0 + lr) << 6) + ls);
        uint4* ad = (uint4*)(As + lr * 72 + ls);
        uint4* bd = (uint4*)(Bs + lr * 72 + ls);
#pragma unroll
        for (int i = 0; i < 4; i++) { ad[i] = qs[i]; bd[i] = ks[i]; }
    }
    __syncthreads();

    int wm = (warp >> 2) * 64, wn = (warp & 3) * 32;
    int amr = lane & 15, akc = (lane >> 4) * 8;
    int bnr = (lane & 7) + ((lane & 16) ? 8 : 0);
    int bkc = (lane & 8) ? 8 : 0;

    float acc[4][4][4] = {};
#pragma unroll
    for (int ks = 0; ks < 4; ks++) {
        int kk = ks * 16;
        uint32_t af[4][4], bf[2][4];
#pragma unroll
        for (int mi = 0; mi < 4; mi++)
            ldm4(af[mi], cvta_s(As + (wm + mi * 16 + amr) * 72 + kk + akc));
#pragma unroll
        for (int np = 0; np < 2; np++)
            ldm4(bf[np], cvta_s(Bs + (wn + np * 16 + bnr) * 72 + kk + bkc));
#pragma unroll
        for (int mi = 0; mi < 4; mi++)
#pragma unroll
            for (int ni = 0; ni < 4; ni++)
                mma16816(acc[mi][ni], af[mi], &bf[ni >> 1][(ni & 1) * 2]);
    }
    __syncthreads();

    __half* stage = s2;
    int row = lane >> 2, colp = (lane & 3) * 2;
#pragma unroll
    for (int mi = 0; mi < 4; mi++)
#pragma unroll
        for (int ni = 0; ni < 4; ni++) {
            int rr = wm + mi * 16 + row, cc = wn + ni * 8 + colp;
            *(__half2*)&stage[rr * 136 + cc] =
                __floats2half2_rn(acc[mi][ni][0], acc[mi][ni][1]);
            *(__half2*)&stage[(rr + 8) * 136 + cc] =
                __floats2half2_rn(acc[mi][ni][2], acc[mi][ni][3]);
        }
    __syncthreads();

    // fp8 bulk store: 128 rows x 128 fp8 = 1024 uint4 (16 fp8 each)
    uint8_t* Jp = g_J + ((size_t)bh << 20);
#pragma unroll
    for (int i = 0; i < 4; i++) {
        int idx = i * 256 + t;                 // 0..1023
        int rr = idx >> 3, chunk = idx & 7;    // chunk of 16 fp8
        uint4 v = h16_to_f8x16((const uint32_t*)&stage[rr * 136 + chunk * 16]);
        *(uint4*)&Jp[(size_t)(q0 + rr) * 1024 + k0 + chunk * 16] = v;
    }
}

// ====== K34: per (b,q): EL = J@Wl - mask, softmax over k, U = W@Ww — all HMMA ======
#define JST 1032
__global__ __launch_bounds__(256) void k34_softmax_U(const float* __restrict__ mask,
                                                     const float* __restrict__ Wl,
                                                     const float* __restrict__ Ww) {
    extern __shared__ __half sJ[];
    __shared__ __half sWl[16 * 24];
    __shared__ __half sWwS[16 * 24];
    __shared__ float sMask[1024];
    __shared__ float red[8][16];
    __shared__ float sInv[16];

    int q = blockIdx.x, b = blockIdx.y;
    int tid = threadIdx.x, lane = tid & 31, w = tid >> 5;
    const uint8_t* Jb = g_J + (size_t)b * 16777216 + (size_t)q * 1024;

    { int h = tid >> 4, g = tid & 15; sWl[h * 24 + g] = __float2half(Wl[h * 16 + g]); }
    { float4 m4 = *(const float4*)(mask + b * 1024 + tid * 4);
      *(float4*)&sMask[tid * 4] = m4; }
    // load J planes (fp8 -> fp16): each plane 1024 fp8 = 64 uint4; 32 lanes x 2 it
#pragma unroll
    for (int p = 0; p < 2; p++) {
        int h = w * 2 + p;
        const uint4* src = (const uint4*)(Jb + (size_t)h * 1048576);
#pragma unroll
        for (int it = 0; it < 2; it++) {
            int c16 = lane + it * 32;          // 0..63 : chunk of 16 elements
            uint4 hv[2];
            f8x16_to_h16(src[c16], hv);
            *(uint4*)&sJ[h * JST + c16 * 16]     = hv[0];
            *(uint4*)&sJ[h * JST + c16 * 16 + 8] = hv[1];
        }
    }
    __syncthreads();

    // ---- phase 1 ----
    uint32_t bWl[4];
    {
        int b_r = (lane & 7) + ((lane & 8) ? 8 : 0);
        int b_c = (lane & 16) ? 8 : 0;
        ldm4t(bWl, cvta_s(sWl + b_r * 24 + b_c));
    }
    int a_r = (lane & 7) + ((lane & 16) ? 8 : 0);
    int a_c = (lane & 8) ? 8 : 0;
    int r = lane >> 2, cg = (lane & 3) * 2;
    int kbase = w * 128;
    float psum4[4] = {};
#pragma unroll
    for (int i = 0; i < 8; i++) {
        int kcol = kbase + i * 16;
        uint32_t af[4];
        ldm4t(af, cvta_s(sJ + a_r * JST + kcol + a_c));
        float c0[4] = {}, c1[4] = {};
        mma16816(c0, af, &bWl[0]);
        mma16816(c1, af, &bWl[2]);
        float mk0 = sMask[kcol + r], mk1 = sMask[kcol + r + 8];
        float e00 = fast_exp(c0[0] - mk0), e01 = fast_exp(c0[1] - mk0);
        float e02 = fast_exp(c0[2] - mk1), e03 = fast_exp(c0[3] - mk1);
        float e10 = fast_exp(c1[0] - mk0), e11 = fast_exp(c1[1] - mk0);
        float e12 = fast_exp(c1[2] - mk1), e13 = fast_exp(c1[3] - mk1);
        psum4[0] += e00 + e02; psum4[1] += e01 + e03;
        psum4[2] += e10 + e12; psum4[3] += e11 + e13;
        *(__half2*)&sJ[r * JST + kcol + cg]           = __floats2half2_rn(e00, e01);
        *(__half2*)&sJ[(r + 8) * JST + kcol + cg]     = __floats2half2_rn(e02, e03);
        *(__half2*)&sJ[r * JST + kcol + 8 + cg]       = __floats2half2_rn(e10, e11);
        *(__half2*)&sJ[(r + 8) * JST + kcol + 8 + cg] = __floats2half2_rn(e12, e13);
    }
#pragma unroll
    for (int s = 16; s >= 4; s >>= 1) {
#pragma unroll
        for (int j = 0; j < 4; j++)
            psum4[j] += __shfl_xor_sync(0xffffffffu, psum4[j], s);
    }
    if (lane < 4) {
        red[w][2 * lane]     = psum4[0];
        red[w][2 * lane + 1] = psum4[1];
        red[w][2 * lane + 8] = psum4[2];
        red[w][2 * lane + 9] = psum4[3];
    }
    __syncthreads();
    if (tid < 16) {
        float s = 0.f;
#pragma unroll
        for (int ww = 0; ww < 8; ww++) s += red[ww][tid];
        sInv[tid] = USCALE / s;
    }
    __syncthreads();
    { int v = tid >> 4, g = tid & 15;
      sWwS[v * 24 + g] = __float2half(sInv[g] * Ww[g * 16 + v]); }
    __syncthreads();

    // ---- phase 2: stage U into sJ overlay, then fp8 bulk stores ----
    uint32_t aW[4];
    { int amr = lane & 15, akc2 = (lane >> 4) * 8;
      ldm4(aW, cvta_s(sWwS + amr * 24 + akc2)); }
    int bnr = (lane & 7) + ((lane & 16) ? 8 : 0);
    int bkc = (lane & 8) ? 8 : 0;
#pragma unroll
    for (int i = 0; i < 8; i++) {
        int kcol = kbase + i * 16;
        uint32_t bf[4];
        ldm4(bf, cvta_s(sJ + bnr * JST + kcol + bkc));
        float c0[4] = {}, c1[4] = {};
        mma16816(c0, aW, &bf[0]);
        mma16816(c1, aW, &bf[2]);
        __syncwarp();
        *(__half2*)&sJ[r * JST + kcol + cg]           = __floats2half2_rn(c0[0], c0[1]);
        *(__half2*)&sJ[(r + 8) * JST + kcol + cg]     = __floats2half2_rn(c0[2], c0[3]);
        *(__half2*)&sJ[r * JST + kcol + 8 + cg]       = __floats2half2_rn(c1[0], c1[1]);
        *(__half2*)&sJ[(r + 8) * JST + kcol + 8 + cg] = __floats2half2_rn(c1[2], c1[3]);
    }
    __syncwarp();
    uint8_t* Ub = g_U + (size_t)b * 16777216 + (size_t)q * 1024;
#pragma unroll
    for (int it = 0; it < 4; it++) {
        int idx = lane + it * 32;              // 0..127 : 16 v-rows x 8 chunks(16 fp8)
        int v = idx >> 3, uu = (idx & 7) * 16;
        uint4 o = h16_to_f8x16((const uint32_t*)&sJ[v * JST + kbase + uu]);
        *(uint4*)&Ub[(size_t)v * 1048576 + kbase + uu] = o;
    }
}

// ================= K5: O = U.V per (b,v), HMMA, 128x64, KC=64 DB, fp8 U in =========
__global__ __launch_bounds__(256) void k5_O() {
    extern __shared__ __half sm5[];
    __half* Asb[2] = { sm5, sm5 + 128 * 72 };
    __half* Bsb[2] = { sm5 + 2 * 128 * 72, sm5 + 2 * 128 * 72 + 64 * 72 };
    int bv = blockIdx.y;
    int b = bv >> 4, v = bv & 15;
    int q0 = blockIdx.x * 128;
    const uint8_t* U = g_U + ((size_t)bv << 20);
    const __half* Vb = g_Vh + ((size_t)bv << 16);

    int t = threadIdx.x, lane = t & 31, warp = t >> 5;
    int alr = t >> 1, als = (t & 1) * 32;   // A: 32 fp8 = 2 raw uint4 -> 4 smem uint4
    int blr = t >> 2, bls = (t & 3) * 16;

    {
        const uint4* as = (const uint4*)(U + (size_t)(q0 + alr) * 1024 + als);
        uint4* ad = (uint4*)(Asb[0] + alr * 72 + als);
        uint4 cv[2];
        f8x16_to_h16(as[0], cv); ad[0] = cv[0]; ad[1] = cv[1];
        f8x16_to_h16(as[1], cv); ad[2] = cv[0]; ad[3] = cv[1];
        const uint4* bs = (const uint4*)(Vb + (blr << 6) + bls);
        uint4* bd = (uint4*)(Bsb[0] + blr * 72 + bls);
        bd[0] = bs[0]; bd[1] = bs[1];
    }
    __syncthreads();

    int wm = (warp >> 1) * 32, wn = (warp & 1) * 32;
    int amr = lane & 15, akc = (lane >> 4) * 8;
    int btr = (lane & 7) + ((lane & 8) ? 8 : 0);
    int btc = (lane & 16) ? 8 : 0;

    float acc[2][4][4] = {};
    for (int ch = 0; ch < 16; ch++) {
        int buf = ch & 1;
        uint4 pa[2], pb[2];
        if (ch < 15) {
            int kn = (ch + 1) * 64;
            const uint4* as = (const uint4*)(U + (size_t)(q0 + alr) * 1024 + kn + als);
            pa[0] = as[0]; pa[1] = as[1];
            const uint4* bs = (const uint4*)(Vb + ((kn + blr) << 6) + bls);
            pb[0] = bs[0]; pb[1] = bs[1];
        }
#pragma unroll
        for (int ks = 0; ks < 4; ks++) {
            int kk = ks * 16;
            uint32_t af[2][4], bf[2][4];
#pragma unroll
            for (int mi = 0; mi < 2; mi++)
                ldm4(af[mi], cvta_s(Asb[buf] + (wm + mi * 16 + amr) * 72 + kk + akc));
#pragma unroll
            for (int np = 0; np < 2; np++)
                ldm4t(bf[np], cvta_s(Bsb[buf] + (kk + btr) * 72 + wn + np * 16 + btc));
#pragma unroll
            for (int mi = 0; mi < 2; mi++)
#pragma unroll
                for (int ni = 0; ni < 4; ni++)
                    mma16816(acc[mi][ni], af[mi], &bf[ni >> 1][(ni & 1) * 2]);
        }
        if (ch < 15) {
            int nb = buf ^ 1;
            uint4* ad = (uint4*)(Asb[nb] + alr * 72 + als);
            uint4 cv[2];
            f8x16_to_h16(pa[0], cv); ad[0] = cv[0]; ad[1] = cv[1];
            f8x16_to_h16(pa[1], cv); ad[2] = cv[0]; ad[3] = cv[1];
            uint4* bd = (uint4*)(Bsb[nb] + blr * 72 + bls);
            bd[0] = pb[0]; bd[1] = pb[1];
        }
        __syncthreads();
    }

    int row = lane >> 2, colp = (lane & 3) * 2;
#pragma unroll
    for (int mi = 0; mi < 2; mi++) {
        int q = q0 + wm + mi * 16 + row;
#pragma unroll
        for (int ni = 0; ni < 4; ni++) {
            int d = wn + ni * 8 + colp;
            __half* p = g_Oh + b * 1048576 + q * 1024 + v * 64 + d;
            *(__half2*)p = __floats2half2_rn(acc[mi][ni][0] * UINV, acc[mi][ni][1] * UINV);
            *(__half2*)(p + 8 * 1024) =
                __floats2half2_rn(acc[mi][ni][2] * UINV, acc[mi][ni][3] * UINV);
        }
    }
}

// ================= K6: out[b,c,q] = inp + O @ Wo16, HMMA 64q x 64c, KC=64 DB =======
__global__ __launch_bounds__(256) void k6_out(const float* __restrict__ inp,
                                              float* __restrict__ out) {
    extern __shared__ __half sm6[];
    __half* Asb[2] = { sm6, sm6 + 64 * 72 };
    __half* Bsb[2] = { sm6 + 2 * 64 * 72, sm6 + 2 * 64 * 72 + 64 * 72 };
    float* Cs = (float*)sm6;
    int b = blockIdx.z;
    int c0 = blockIdx.x * 64, q0 = blockIdx.y * 64;
    const __half* Oq = g_Oh + b * 1048576;

    int t = threadIdx.x, lane = t & 31, w = t >> 5;
    int lr = t >> 2, ls = (t & 3) * 16;

    {
        const uint4* as = (const uint4*)(Oq + (q0 + lr) * 1024 + ls);
        uint4* ad = (uint4*)(Asb[0] + lr * 72 + ls);
        ad[0] = as[0]; ad[1] = as[1];
        const uint4* bs = (const uint4*)(g_Wo16 + lr * 512 + c0 + ls);
        uint4* bd = (uint4*)(Bsb[0] + lr * 72 + ls);
        bd[0] = bs[0]; bd[1] = bs[1];
    }
    __syncthreads();

    int wm = (w >> 2) * 32, wn = (w & 3) * 16;
    int amr = lane & 15, akc = (lane >> 4) * 8;
    int b_r = (lane & 7) + ((lane & 8) ? 8 : 0);
    int b_c = (lane & 16) ? 8 : 0;

    float acc[2][2][4] = {};
    for (int ch = 0; ch < 16; ch++) {
        int buf = ch & 1;
        uint4 pa[2], pb[2];
        if (ch < 15) {
            int kn = (ch + 1) * 64;
            const uint4* as = (const uint4*)(Oq + (q0 + lr) * 1024 + kn + ls);
            pa[0] = as[0]; pa[1] = as[1];
            const uint4* bs = (const uint4*)(g_Wo16 + (kn + lr) * 512 + c0 + ls);
            pb[0] = bs[0]; pb[1] = bs[1];
        }
#pragma unroll
        for (int ks = 0; ks < 4; ks++) {
            int kk = ks * 16;
            uint32_t af[2][4], bf[4];
#pragma unroll
            for (int mi = 0; mi < 2; mi++)
                ldm4(af[mi], cvta_s(Asb[buf] + (wm + mi * 16 + amr) * 72 + kk + akc));
            ldm4t(bf, cvta_s(Bsb[buf] + (kk + b_r) * 72 + wn + b_c));
#pragma unroll
            for (int mi = 0; mi < 2; mi++)
#pragma unroll
                for (int ni = 0; ni < 2; ni++)
                    mma16816(acc[mi][ni], af[mi], &bf[ni * 2]);
        }
        if (ch < 15) {
            int nb = buf ^ 1;
            uint4* ad = (uint4*)(Asb[nb] + lr * 72 + ls);
            ad[0] = pa[0]; ad[1] = pa[1];
            uint4* bd = (uint4*)(Bsb[nb] + lr * 72 + ls);
            bd[0] = pb[0]; bd[1] = pb[1];
        }
        __syncthreads();
    }

    int row = lane >> 2, cp = (lane & 3) * 2;
#pragma unroll
    for (int mi = 0; mi < 2; mi++)
#pragma unroll
        for (int ni = 0; ni < 2; ni++) {
            int qq = wm + mi * 16 + row;
            int cc2 = wn + ni * 8 + cp;
            Cs[cc2 * 68 + qq]           = acc[mi][ni][0];
            Cs[(cc2 + 1) * 68 + qq]     = acc[mi][ni][1];
            Cs[cc2 * 68 + qq + 8]       = acc[mi][ni][2];
            Cs[(cc2 + 1) * 68 + qq + 8] = acc[mi][ni][3];
        }
    __syncthreads();
#pragma unroll
    for (int i2 = 0; i2 < 4; i2++) {
        int idx = t + i2 * 256;
        int cc2 = idx >> 4, q4 = (idx & 15) * 4;
        size_t off = (size_t)b * 524288 + (size_t)(c0 + cc2) * 1024 + q0 + q4;
        float4 iv = *(const float4*)(inp + off);
        *(float4*)(out + off) = make_float4(iv.x + Cs[cc2 * 68 + q4],
                                            iv.y + Cs[cc2 * 68 + q4 + 1],
                                            iv.z + Cs[cc2 * 68 + q4 + 2],
                                            iv.w + Cs[cc2 * 68 + q4 + 3]);
    }
}

// ================= launch =================
extern "C" void kernel_launch(void* const* d_in, const int* in_sizes, int n_in,
                              void* d_out, int out_size) {
    const float* inp  = (const float*)d_in[0];
    const float* mask = (const float*)d_in[1];
    const float* Wq   = (const float*)d_in[2];
    const float* Wk   = (const float*)d_in[3];
    const float* Wv   = (const float*)d_in[4];
    const float* aq   = (const float*)d_in[5];
    const float* ak   = (const float*)d_in[6];
    const float* av   = (const float*)d_in[7];
    const float* Wl   = (const float*)d_in[8];
    const float* Ww   = (const float*)d_in[9];
    const float* Wo   = (const float*)d_in[10];
    float* out = (float*)d_out;

    const int SMEM_K34 = 16 * JST * 2;                        // 33024
    const int SMEM_K5  = (2 * 128 * 72 + 2 * 64 * 72) * 2;    // 55296
    const int SMEM_K6  = 4 * 64 * 72 * 2;                     // 36864
    cudaFuncSetAttribute(k34_softmax_U, cudaFuncAttributeMaxDynamicSharedMemorySize, SMEM_K34);
    cudaFuncSetAttribute(k5_O, cudaFuncAttributeMaxDynamicSharedMemorySize, SMEM_K5);
    cudaFuncSetAttribute(k6_out, cudaFuncAttributeMaxDynamicSharedMemorySize, SMEM_K6);

    kc0<<<3264, 256>>>(inp, Wq, Wk, Wv, aq, ak, av, Wo);
    k1_proj<<<dim3(8, 8, 6), 256>>>();
    k2_J<<<dim3(8, 8, 32), 256>>>();
    k34_softmax_U<<<dim3(1024, 2), 256, SMEM_K34>>>(mask, Wl, Ww);
    k5_O<<<dim3(8, 32), 256, SMEM_K5>>>();
    k6_out<<<dim3(8, 16, 2), 256, SMEM_K6>>>(inp, out);
}

// round 16
// speedup vs baseline: 1.1145x; 1.0029x over previous
#include <cuda_runtime.h>
#include <cuda_fp16.h>
#include <cstdint>
#include <cstring>

#define CIN 512
#define SEQ 1024

// ---------------- scratch ----------------
__device__ __half  g_inp16[2 * 512 * 1024];            // [b][c][s]
__device__ __half  g_W16[3 * 512 * 1024];              // [w][c][h*64+d] scale-folded
__device__ __half  g_Wo16[1024 * 512];                 // [j'=v*64+d][c]
__device__ __half  g_Qh[2 * 16 * 1024 * 64];           // [b][h][s][d]
__device__ __half  g_Kh[2 * 16 * 1024 * 64];           // [b][h][s][d]
__device__ __half  g_Vh[2 * 16 * 1024 * 64];           // [b][h][k][d]
__device__ uint8_t g_J[(size_t)2 * 16 * 1024 * 1024];  // [b][h][q][k] e4m3, 32 MB
__device__ uint8_t g_U[(size_t)2 * 16 * 1024 * 1024];  // [b][v][q][k] e4m3 (x65536), 32 MB
__device__ __half  g_Oh[2 * 1024 * 1024];              // [b][q][v*64+d] fp16

#define USCALE 65536.0f
#define UINV   (1.0f / 65536.0f)

// ---------------- exp via MUFU ----------------
__device__ __forceinline__ float fast_exp(float x) {
    float r;
    asm("ex2.approx.f32 %0, %1;" : "=f"(r) : "f"(x * 1.4426950408889634f));
    return r;
}

// bit-cast half2 -> uint32
__device__ __forceinline__ uint32_t h2u(__half2 h) {
    uint32_t u;
    memcpy(&u, &h, 4);
    return u;
}

// ---------------- fp8 converts (HW cvt, sm_89+) ----------------
__device__ __forceinline__ uint16_t h2_to_e4m3x2(uint32_t h2) {
    uint16_t r;
    asm("cvt.rn.satfinite.e4m3x2.f16x2 %0, %1;" : "=h"(r) : "r"(h2));
    return r;
}
__device__ __forceinline__ uint32_t e4m3x2_to_h2(uint16_t u) {
    uint32_t r;
    asm("cvt.rn.f16x2.e4m3x2 %0, %1;" : "=r"(r) : "h"(u));
    return r;
}
__device__ __forceinline__ void f8x16_to_h16(uint4 raw, uint4* o) {
    uint16_t* pr = (uint16_t*)&raw;
    uint32_t hh[8];
#pragma unroll
    for (int e = 0; e < 8; e++) hh[e] = e4m3x2_to_h2(pr[e]);
    o[0] = *(uint4*)&hh[0];
    o[1] = *(uint4*)&hh[4];
}
__device__ __forceinline__ uint4 h16_to_f8x16(const uint32_t* hsrc) {
    uint16_t e[8];
#pragma unroll
    for (int p = 0; p < 8; p++) e[p] = h2_to_e4m3x2(hsrc[p]);
    return *(uint4*)e;
}

// ---------------- mma helpers ----------------
__device__ __forceinline__ uint32_t cvta_s(const void* p) {
    return (uint32_t)__cvta_generic_to_shared(p);
}
__device__ __forceinline__ void ldm4(uint32_t* r, uint32_t a) {
    asm volatile("ldmatrix.sync.aligned.m8n8.x4.shared.b16 {%0,%1,%2,%3}, [%4];"
        : "=r"(r[0]), "=r"(r[1]), "=r"(r[2]), "=r"(r[3]) : "r"(a));
}
__device__ __forceinline__ void ldm4t(uint32_t* r, uint32_t a) {
    asm volatile("ldmatrix.sync.aligned.m8n8.x4.trans.shared.b16 {%0,%1,%2,%3}, [%4];"
        : "=r"(r[0]), "=r"(r[1]), "=r"(r[2]), "=r"(r[3]) : "r"(a));
}
__device__ __forceinline__ void mma16816(float* c, const uint32_t* a, const uint32_t* b) {
    asm volatile("mma.sync.aligned.m16n8k16.row.col.f32.f16.f16.f32 "
        "{%0,%1,%2,%3}, {%4,%5,%6,%7}, {%8,%9}, {%0,%1,%2,%3};"
        : "+f"(c[0]), "+f"(c[1]), "+f"(c[2]), "+f"(c[3])
        : "r"(a[0]), "r"(a[1]), "r"(a[2]), "r"(a[3]), "r"(b[0]), "r"(b[1]));
}

// ================= KC0: fp16 conversions + weight reorders =================
__global__ __launch_bounds__(256) void kc0(const float* __restrict__ inp,
        const float* __restrict__ Wq, const float* __restrict__ Wk,
        const float* __restrict__ Wv,
        const float* __restrict__ aq, const float* __restrict__ ak,
        const float* __restrict__ av, const float* __restrict__ Wo) {
    int bid = blockIdx.x, tid = threadIdx.x;
    if (bid < 2048) {
        int t = bid * 256 + tid;
        float2 v = *(const float2*)(inp + (size_t)t * 2);
        *(__half2*)(g_inp16 + (size_t)t * 2) = __floats2half2_rn(v.x, v.y);
        return;
    }
    if (bid < 2240) {
        __shared__ __half sT[8 * 1024];
        int u = bid - 2048;
        int w = u >> 6, r0 = (u & 63) * 8;
        const float* W = (w == 0) ? Wq : ((w == 1) ? Wk : Wv);
        float al = (w == 0) ? aq[0] : ((w == 1) ? ak[0] : av[0]);
        float sc = 1.0f / (1.0f + fast_exp(-al));
#pragma unroll
        for (int i = 0; i < 8; i++) {
            int idx = i * 256 + tid;
            int row = idx >> 8, col4 = (idx & 255) * 4;
            float4 v = *(const float4*)&W[(r0 + row) * 1024 + col4];
            __half* d = &sT[row * 1024 + col4];
            d[0] = __float2half_rn(v.x * sc);
            d[1] = __float2half_rn(v.y * sc);
            d[2] = __float2half_rn(v.z * sc);
            d[3] = __float2half_rn(v.w * sc);
        }
        __syncthreads();
#pragma unroll
        for (int i = 0; i < 4; i++) {
            int idx = i * 256 + tid;
            int row = idx >> 7, jo8 = (idx & 127) * 8;
            __half outv[8];
#pragma unroll
            for (int e = 0; e < 8; e++) {
                int jp = jo8 + e;
                outv[e] = sT[row * 1024 + (jp & 63) * 16 + (jp >> 6)];
            }
            *(uint4*)&g_W16[w * 524288 + (r0 + row) * 1024 + jo8] = *(uint4*)outv;
        }
        return;
    }
    {
        int u2 = (bid - 2240) * 256 + tid;
        int jp = u2 >> 8, cp = (u2 & 255) * 2;
        int wrow = ((jp & 63) << 4) | (jp >> 6);
        *(__half2*)(g_Wo16 + jp * 512 + cp) =
            __floats2half2_rn(Wo[wrow * 512 + cp], Wo[wrow * 512 + cp + 1]);
    }
}

// ================= K1: QKV projection, HMMA, 128x128, KC=32 DB, staged epilogue ====
__global__ __launch_bounds__(256) void k1_proj() {
    __shared__ __half s1[17408];
    __half* Asb[2] = { s1, s1 + 4352 };
    __half* Bsb[2] = { s1 + 8704, s1 + 13056 };
    int z = blockIdx.z;
    int b = z / 3, w = z % 3;
    int n0 = blockIdx.x * 128, m0 = blockIdx.y * 128;
    const __half* Ag = g_inp16 + b * 524288;
    const __half* Bg = g_W16 + w * 524288;

    int t = threadIdx.x, lane = t & 31, warp = t >> 5;
    int lrow = t >> 3, lcol = (t & 7) * 16;

    {
        const uint4* as = (const uint4*)(Ag + lrow * 1024 + m0 + lcol);
        const uint4* bs = (const uint4*)(Bg + lrow * 1024 + n0 + lcol);
        uint4* ad = (uint4*)(Asb[0] + lrow * 136 + lcol);
        uint4* bd = (uint4*)(Bsb[0] + lrow * 136 + lcol);
        ad[0] = as[0]; ad[1] = as[1];
        bd[0] = bs[0]; bd[1] = bs[1];
    }
    __syncthreads();

    int wm = (warp >> 2) * 64, wn = (warp & 3) * 32;
    int a_r = (lane & 7) + ((lane & 16) ? 8 : 0);
    int a_c = (lane & 8) ? 8 : 0;
    int b_r = (lane & 7) + ((lane & 8) ? 8 : 0);
    int b_c = (lane & 16) ? 8 : 0;

    float acc[4][4][4] = {};
    for (int ch = 0; ch < 16; ch++) {
        int buf = ch & 1;
        uint4 pa0, pa1, pb0, pb1;
        if (ch < 15) {
            const uint4* as = (const uint4*)(Ag + ((ch + 1) * 32 + lrow) * 1024 + m0 + lcol);
            const uint4* bs = (const uint4*)(Bg + ((ch + 1) * 32 + lrow) * 1024 + n0 + lcol);
            pa0 = as[0]; pa1 = as[1];
            pb0 = bs[0]; pb1 = bs[1];
        }
#pragma unroll
        for (int ks = 0; ks < 2; ks++) {
            int kk = ks * 16;
            uint32_t af[4][4], bf[2][4];
#pragma unroll
            for (int mi = 0; mi < 4; mi++)
                ldm4t(af[mi], cvta_s(Asb[buf] + (kk + a_r) * 136 + wm + mi * 16 + a_c));
#pragma unroll
            for (int np = 0; np < 2; np++)
                ldm4t(bf[np], cvta_s(Bsb[buf] + (kk + b_r) * 136 + wn + np * 16 + b_c));
#pragma unroll
            for (int mi = 0; mi < 4; mi++)
#pragma unroll
                for (int ni = 0; ni < 4; ni++)
                    mma16816(acc[mi][ni], af[mi], &bf[ni >> 1][(ni & 1) * 2]);
        }
        if (ch < 15) {
            int nb = buf ^ 1;
            uint4* ad = (uint4*)(Asb[nb] + lrow * 136 + lcol);
            uint4* bd = (uint4*)(Bsb[nb] + lrow * 136 + lcol);
            ad[0] = pa0; ad[1] = pa1;
            bd[0] = pb0; bd[1] = pb1;
        }
        __syncthreads();
    }

    __half* stage = s1;
    int row = lane >> 2, colp = (lane & 3) * 2;
#pragma unroll
    for (int mi = 0; mi < 4; mi++)
#pragma unroll
        for (int ni = 0; ni < 4; ni++) {
            int rr = wm + mi * 16 + row, cc = wn + ni * 8 + colp;
            *(__half2*)&stage[rr * 136 + cc] =
                __floats2half2_rn(acc[mi][ni][0], acc[mi][ni][1]);
            *(__half2*)&stage[(rr + 8) * 136 + cc] =
                __floats2half2_rn(acc[mi][ni][2], acc[mi][ni][3]);
        }
    __syncthreads();

    __half* base = (w == 0) ? g_Qh : ((w == 1) ? g_Kh : g_Vh);
#pragma unroll
    for (int i = 0; i < 8; i++) {
        int idx = i * 256 + t;
        int rr = idx >> 4, chunk = idx & 15;
        int jp = n0 + chunk * 8;
        int h = jp >> 6, d = jp & 63;
        *(uint4*)(base + (((b * 16 + h) * 1024 + m0 + rr) << 6) + d) =
            *(const uint4*)&stage[rr * 136 + chunk * 8];
    }
}

// ================= K2: J = Q.K^T per (b,h), HMMA, staged epilogue, fp8 J out =======
__global__ __launch_bounds__(256) void k2_J() {
    __shared__ __half s2[18432];
    __half* As = s2;
    __half* Bs = s2 + 9216;
    int bh = blockIdx.z;
    int q0 = blockIdx.y * 128, k0 = blockIdx.x * 128;
    const __half* Qb = g_Qh + ((size_t)bh << 16);
    const __half* Kb = g_Kh + ((size_t)bh << 16);

    int t = threadIdx.x, lane = t & 31, warp = t >> 5;
    {
        int lr = t >> 1, ls = (t & 1) * 32;
        const uint4* qs = (const uint4*)(Qb + ((q0 + lr) << 6) + ls);
        const uint4* ks = (const uint4*)(Kb + ((k0 + lr) << 6) + ls);
        uint4* ad = (uint4*)(As + lr * 72 + ls);
        uint4* bd = (uint4*)(Bs + lr * 72 + ls);
#pragma unroll
        for (int i = 0; i < 4; i++) { ad[i] = qs[i]; bd[i] = ks[i]; }
    }
    __syncthreads();

    int wm = (warp >> 2) * 64, wn = (warp & 3) * 32;
    int amr = lane & 15, akc = (lane >> 4) * 8;
    int bnr = (lane & 7) + ((lane & 16) ? 8 : 0);
    int bkc = (lane & 8) ? 8 : 0;

    float acc[4][4][4] = {};
#pragma unroll
    for (int ks = 0; ks < 4; ks++) {
        int kk = ks * 16;
        uint32_t af[4][4], bf[2][4];
#pragma unroll
        for (int mi = 0; mi < 4; mi++)
            ldm4(af[mi], cvta_s(As + (wm + mi * 16 + amr) * 72 + kk + akc));
#pragma unroll
        for (int np = 0; np < 2; np++)
            ldm4(bf[np], cvta_s(Bs + (wn + np * 16 + bnr) * 72 + kk + bkc));
#pragma unroll
        for (int mi = 0; mi < 4; mi++)
#pragma unroll
            for (int ni = 0; ni < 4; ni++)
                mma16816(acc[mi][ni], af[mi], &bf[ni >> 1][(ni & 1) * 2]);
    }
    __syncthreads();

    __half* stage = s2;
    int row = lane >> 2, colp = (lane & 3) * 2;
#pragma unroll
    for (int mi = 0; mi < 4; mi++)
#pragma unroll
        for (int ni = 0; ni < 4; ni++) {
            int rr = wm + mi * 16 + row, cc = wn + ni * 8 + colp;
            *(__half2*)&stage[rr * 136 + cc] =
                __floats2half2_rn(acc[mi][ni][0], acc[mi][ni][1]);
            *(__half2*)&stage[(rr + 8) * 136 + cc] =
                __floats2half2_rn(acc[mi][ni][2], acc[mi][ni][3]);
        }
    __syncthreads();

    uint8_t* Jp = g_J + ((size_t)bh << 20);
#pragma unroll
    for (int i = 0; i < 4; i++) {
        int idx = i * 256 + t;                 // 0..1023
        int rr = idx >> 3, chunk = idx & 7;    // chunk of 16 fp8
        uint4 v = h16_to_f8x16((const uint32_t*)&stage[rr * 136 + chunk * 16]);
        *(uint4*)&Jp[(size_t)(q0 + rr) * 1024 + k0 + chunk * 16] = v;
    }
}

// ====== K34: EL = J@Wl - mask, softmax, U = W@Ww — exp kept in registers ======
// Phase-1 C-fragment (m=kpos,n=g) == phase-2 B-fragment (n=kpos,k=g) thread-for-
// thread, so exp outputs feed phase-2 MMAs directly; no smem relay for e.
#define JST 1032
__global__ __launch_bounds__(256) void k34_softmax_U(const float* __restrict__ mask,
                                                     const float* __restrict__ Wl,
                                                     const float* __restrict__ Ww) {
    extern __shared__ __half sJ[];
    __shared__ __half sWl[16 * 24];
    __shared__ __half sWwS[16 * 24];
    __shared__ float sMask[1024];
    __shared__ float red[8][16];
    __shared__ float sInv[16];

    int q = blockIdx.x, b = blockIdx.y;
    int tid = threadIdx.x, lane = tid & 31, w = tid >> 5;
    const uint8_t* Jb = g_J + (size_t)b * 16777216 + (size_t)q * 1024;

    { int h = tid >> 4, g = tid & 15; sWl[h * 24 + g] = __float2half(Wl[h * 16 + g]); }
    { float4 m4 = *(const float4*)(mask + b * 1024 + tid * 4);
      *(float4*)&sMask[tid * 4] = m4; }
#pragma unroll
    for (int p = 0; p < 2; p++) {
        int h = w * 2 + p;
        const uint4* src = (const uint4*)(Jb + (size_t)h * 1048576);
#pragma unroll
        for (int it = 0; it < 2; it++) {
            int c16 = lane + it * 32;
            uint4 hv[2];
            f8x16_to_h16(src[c16], hv);
            *(uint4*)&sJ[h * JST + c16 * 16]     = hv[0];
            *(uint4*)&sJ[h * JST + c16 * 16 + 8] = hv[1];
        }
    }
    __syncthreads();

    // ---- phase 1: EL tiles + exp; e stays in registers as phase-2 B frags ----
    uint32_t bWl[4];
    {
        int b_r = (lane & 7) + ((lane & 8) ? 8 : 0);
        int b_c = (lane & 16) ? 8 : 0;
        ldm4t(bWl, cvta_s(sWl + b_r * 24 + b_c));
    }
    int a_r = (lane & 7) + ((lane & 16) ? 8 : 0);
    int a_c = (lane & 8) ? 8 : 0;
    int r = lane >> 2, cg = (lane & 3) * 2;
    int kbase = w * 128;
    float psum4[4] = {};
    uint32_t eh[8][4];          // [tile][b-frag reg]: packed half2 e values
#pragma unroll
    for (int i = 0; i < 8; i++) {
        int kcol = kbase + i * 16;
        uint32_t af[4];
        ldm4t(af, cvta_s(sJ + a_r * JST + kcol + a_c));
        float c0[4] = {}, c1[4] = {};
        mma16816(c0, af, &bWl[0]);   // g 0-7
        mma16816(c1, af, &bWl[2]);   // g 8-15
        float mk0 = sMask[kcol + r], mk1 = sMask[kcol + r + 8];
        float e00 = fast_exp(c0[0] - mk0), e01 = fast_exp(c0[1] - mk0);
        float e02 = fast_exp(c0[2] - mk1), e03 = fast_exp(c0[3] - mk1);
        float e10 = fast_exp(c1[0] - mk0), e11 = fast_exp(c1[1] - mk0);
        float e12 = fast_exp(c1[2] - mk1), e13 = fast_exp(c1[3] - mk1);
        psum4[0] += e00 + e02; psum4[1] += e01 + e03;
        psum4[2] += e10 + e12; psum4[3] += e11 + e13;
        // phase-2 B fragment: b0=(kpos r, g cg..), b1=(kpos r, g 8+cg..),
        //                     b2=(kpos r+8, g cg..), b3=(kpos r+8, g 8+cg..)
        eh[i][0] = h2u(__floats2half2_rn(e00, e01));
        eh[i][1] = h2u(__floats2half2_rn(e10, e11));
        eh[i][2] = h2u(__floats2half2_rn(e02, e03));
        eh[i][3] = h2u(__floats2half2_rn(e12, e13));
    }
#pragma unroll
    for (int s = 16; s >= 4; s >>= 1) {
#pragma unroll
        for (int j = 0; j < 4; j++)
            psum4[j] += __shfl_xor_sync(0xffffffffu, psum4[j], s);
    }
    if (lane < 4) {
        red[w][2 * lane]     = psum4[0];
        red[w][2 * lane + 1] = psum4[1];
        red[w][2 * lane + 8] = psum4[2];
        red[w][2 * lane + 9] = psum4[3];
    }
    __syncthreads();
    if (tid < 16) {
        float s = 0.f;
#pragma unroll
        for (int ww = 0; ww < 8; ww++) s += red[ww][tid];
        sInv[tid] = USCALE / s;
    }
    __syncthreads();
    { int v = tid >> 4, g = tid & 15;
      sWwS[v * 24 + g] = __float2half(sInv[g] * Ww[g * 16 + v]); }
    __syncthreads();

    // ---- phase 2: U^T tiles from register B-frags; stage fp16, fp8 bulk store ----
    uint32_t aW[4];
    { int amr = lane & 15, akc2 = (lane >> 4) * 8;
      ldm4(aW, cvta_s(sWwS + amr * 24 + akc2)); }
#pragma unroll
    for (int i = 0; i < 8; i++) {
        int kcol = kbase + i * 16;
        float c0[4] = {}, c1[4] = {};
        mma16816(c0, aW, &eh[i][0]);   // kpos 0-7 of tile
        mma16816(c1, aW, &eh[i][2]);   // kpos 8-15 of tile
        *(__half2*)&sJ[r * JST + kcol + cg]           = __floats2half2_rn(c0[0], c0[1]);
        *(__half2*)&sJ[(r + 8) * JST + kcol + cg]     = __floats2half2_rn(c0[2], c0[3]);
        *(__half2*)&sJ[r * JST + kcol + 8 + cg]       = __floats2half2_rn(c1[0], c1[1]);
        *(__half2*)&sJ[(r + 8) * JST + kcol + 8 + cg] = __floats2half2_rn(c1[2], c1[3]);
    }
    __syncwarp();
    uint8_t* Ub = g_U + (size_t)b * 16777216 + (size_t)q * 1024;
#pragma unroll
    for (int it = 0; it < 4; it++) {
        int idx = lane + it * 32;              // 0..127 : 16 v-rows x 8 chunks(16 fp8)
        int v = idx >> 3, uu = (idx & 7) * 16;
        uint4 o = h16_to_f8x16((const uint32_t*)&sJ[v * JST + kbase + uu]);
        *(uint4*)&Ub[(size_t)v * 1048576 + kbase + uu] = o;
    }
}

// ================= K5: O = U.V per (b,v), HMMA, 128x64, KC=64 DB, fp8 U in =========
__global__ __launch_bounds__(256) void k5_O() {
    extern __shared__ __half sm5[];
    __half* Asb[2] = { sm5, sm5 + 128 * 72 };
    __half* Bsb[2] = { sm5 + 2 * 128 * 72, sm5 + 2 * 128 * 72 + 64 * 72 };
    int bv = blockIdx.y;
    int b = bv >> 4, v = bv & 15;
    int q0 = blockIdx.x * 128;
    const uint8_t* U = g_U + ((size_t)bv << 20);
    const __half* Vb = g_Vh + ((size_t)bv << 16);

    int t = threadIdx.x, lane = t & 31, warp = t >> 5;
    int alr = t >> 1, als = (t & 1) * 32;
    int blr = t >> 2, bls = (t & 3) * 16;

    {
        const uint4* as = (const uint4*)(U + (size_t)(q0 + alr) * 1024 + als);
        uint4* ad = (uint4*)(Asb[0] + alr * 72 + als);
        uint4 cv[2];
        f8x16_to_h16(as[0], cv); ad[0] = cv[0]; ad[1] = cv[1];
        f8x16_to_h16(as[1], cv); ad[2] = cv[0]; ad[3] = cv[1];
        const uint4* bs = (const uint4*)(Vb + (blr << 6) + bls);
        uint4* bd = (uint4*)(Bsb[0] + blr * 72 + bls);
        bd[0] = bs[0]; bd[1] = bs[1];
    }
    __syncthreads();

    int wm = (warp >> 1) * 32, wn = (warp & 1) * 32;
    int amr = lane & 15, akc = (lane >> 4) * 8;
    int btr = (lane & 7) + ((lane & 8) ? 8 : 0);
    int btc = (lane & 16) ? 8 : 0;

    float acc[2][4][4] = {};
    for (int ch = 0; ch < 16; ch++) {
        int buf = ch & 1;
        uint4 pa[2], pb[2];
        if (ch < 15) {
            int kn = (ch + 1) * 64;
            const uint4* as = (const uint4*)(U + (size_t)(q0 + alr) * 1024 + kn + als);
            pa[0] = as[0]; pa[1] = as[1];
            const uint4* bs = (const uint4*)(Vb + ((kn + blr) << 6) + bls);
            pb[0] = bs[0]; pb[1] = bs[1];
        }
#pragma unroll
        for (int ks = 0; ks < 4; ks++) {
            int kk = ks * 16;
            uint32_t af[2][4], bf[2][4];
#pragma unroll
            for (int mi = 0; mi < 2; mi++)
                ldm4(af[mi], cvta_s(Asb[buf] + (wm + mi * 16 + amr) * 72 + kk + akc));
#pragma unroll
            for (int np = 0; np < 2; np++)
                ldm4t(bf[np], cvta_s(Bsb[buf] + (kk + btr) * 72 + wn + np * 16 + btc));
#pragma unroll
            for (int mi = 0; mi < 2; mi++)
#pragma unroll
                for (int ni = 0; ni < 4; ni++)
                    mma16816(acc[mi][ni], af[mi], &bf[ni >> 1][(ni & 1) * 2]);
        }
        if (ch < 15) {
            int nb = buf ^ 1;
            uint4* ad = (uint4*)(Asb[nb] + alr * 72 + als);
            uint4 cv[2];
            f8x16_to_h16(pa[0], cv); ad[0] = cv[0]; ad[1] = cv[1];
            f8x16_to_h16(pa[1], cv); ad[2] = cv[0]; ad[3] = cv[1];
            uint4* bd = (uint4*)(Bsb[nb] + blr * 72 + bls);
            bd[0] = pb[0]; bd[1] = pb[1];
        }
        __syncthreads();
    }

    int row = lane >> 2, colp = (lane & 3) * 2;
#pragma unroll
    for (int mi = 0; mi < 2; mi++) {
        int q = q0 + wm + mi * 16 + row;
#pragma unroll
        for (int ni = 0; ni < 4; ni++) {
            int d = wn + ni * 8 + colp;
            __half* p = g_Oh + b * 1048576 + q * 1024 + v * 64 + d;
            *(__half2*)p = __floats2half2_rn(acc[mi][ni][0] * UINV, acc[mi][ni][1] * UINV);
            *(__half2*)(p + 8 * 1024) =
                __floats2half2_rn(acc[mi][ni][2] * UINV, acc[mi][ni][3] * UINV);
        }
    }
}

// ================= K6: out[b,c,q] = inp + O @ Wo16, HMMA 64q x 64c, KC=64 DB =======
__global__ __launch_bounds__(256) void k6_out(const float* __restrict__ inp,
                                              float* __restrict__ out) {
    extern __shared__ __half sm6[];
    __half* Asb[2] = { sm6, sm6 + 64 * 72 };
    __half* Bsb[2] = { sm6 + 2 * 64 * 72, sm6 + 2 * 64 * 72 + 64 * 72 };
    float* Cs = (float*)sm6;
    int b = blockIdx.z;
    int c0 = blockIdx.x * 64, q0 = blockIdx.y * 64;
    const __half* Oq = g_Oh + b * 1048576;

    int t = threadIdx.x, lane = t & 31, w = t >> 5;
    int lr = t >> 2, ls = (t & 3) * 16;

    {
        const uint4* as = (const uint4*)(Oq + (q0 + lr) * 1024 + ls);
        uint4* ad = (uint4*)(Asb[0] + lr * 72 + ls);
        ad[0] = as[0]; ad[1] = as[1];
        const uint4* bs = (const uint4*)(g_Wo16 + lr * 512 + c0 + ls);
        uint4* bd = (uint4*)(Bsb[0] + lr * 72 + ls);
        bd[0] = bs[0]; bd[1] = bs[1];
    }
    __syncthreads();

    int wm = (w >> 2) * 32, wn = (w & 3) * 16;
    int amr = lane & 15, akc = (lane >> 4) * 8;
    int b_r = (lane & 7) + ((lane & 8) ? 8 : 0);
    int b_c = (lane & 16) ? 8 : 0;

    float acc[2][2][4] = {};
    for (int ch = 0; ch < 16; ch++) {
        int buf = ch & 1;
        uint4 pa[2], pb[2];
        if (ch < 15) {
            int kn = (ch + 1) * 64;
            const uint4* as = (const uint4*)(Oq + (q0 + lr) * 1024 + kn + ls);
            pa[0] = as[0]; pa[1] = as[1];
            const uint4* bs = (const uint4*)(g_Wo16 + (kn + lr) * 512 + c0 + ls);
            pb[0] = bs[0]; pb[1] = bs[1];
        }
#pragma unroll
        for (int ks = 0; ks < 4; ks++) {
            int kk = ks * 16;
            uint32_t af[2][4], bf[4];
#pragma unroll
            for (int mi = 0; mi < 2; mi++)
                ldm4(af[mi], cvta_s(Asb[buf] + (wm + mi * 16 + amr) * 72 + kk + akc));
            ldm4t(bf, cvta_s(Bsb[buf] + (kk + b_r) * 72 + wn + b_c));
#pragma unroll
            for (int mi = 0; mi < 2; mi++)
#pragma unroll
                for (int ni = 0; ni < 2; ni++)
                    mma16816(acc[mi][ni], af[mi], &bf[ni * 2]);
        }
        if (ch < 15) {
            int nb = buf ^ 1;
            uint4* ad = (uint4*)(Asb[nb] + lr * 72 + ls);
            ad[0] = pa[0]; ad[1] = pa[1];
            uint4* bd = (uint4*)(Bsb[nb] + lr * 72 + ls);
            bd[0] = pb[0]; bd[1] = pb[1];
        }
        __syncthreads();
    }

    int row = lane >> 2, cp = (lane & 3) * 2;
#pragma unroll
    for (int mi = 0; mi < 2; mi++)
#pragma unroll
        for (int ni = 0; ni < 2; ni++) {
            int qq = wm + mi * 16 + row;
            int cc2 = wn + ni * 8 + cp;
            Cs[cc2 * 68 + qq]           = acc[mi][ni][0];
            Cs[(cc2 + 1) * 68 + qq]     = acc[mi][ni][1];
            Cs[cc2 * 68 + qq + 8]       = acc[mi][ni][2];
            Cs[(cc2 + 1) * 68 + qq + 8] = acc[mi][ni][3];
        }
    __syncthreads();
#pragma unroll
    for (int i2 = 0; i2 < 4; i2++) {
        int idx = t + i2 * 256;
        int cc2 = idx >> 4, q4 = (idx & 15) * 4;
        size_t off = (size_t)b * 524288 + (size_t)(c0 + cc2) * 1024 + q0 + q4;
        float4 iv = *(const float4*)(inp + off);
        *(float4*)(out + off) = make_float4(iv.x + Cs[cc2 * 68 + q4],
                                            iv.y + Cs[cc2 * 68 + q4 + 1],
                                            iv.z + Cs[cc2 * 68 + q4 + 2],
                                            iv.w + Cs[cc2 * 68 + q4 + 3]);
    }
}

// ================= launch =================
extern "C" void kernel_launch(void* const* d_in, const int* in_sizes, int n_in,
                              void* d_out, int out_size) {
    const float* inp  = (const float*)d_in[0];
    const float* mask = (const float*)d_in[1];
    const float* Wq   = (const float*)d_in[2];
    const float* Wk   = (const float*)d_in[3];
    const float* Wv   = (const float*)d_in[4];
    const float* aq   = (const float*)d_in[5];
    const float* ak   = (const float*)d_in[6];
    const float* av   = (const float*)d_in[7];
    const float* Wl   = (const float*)d_in[8];
    const float* Ww   = (const float*)d_in[9];
    const float* Wo   = (const float*)d_in[10];
    float* out = (float*)d_out;

    const int SMEM_K34 = 16 * JST * 2;                        // 33024
    const int SMEM_K5  = (2 * 128 * 72 + 2 * 64 * 72) * 2;    // 55296
    const int SMEM_K6  = 4 * 64 * 72 * 2;                     // 36864
    cudaFuncSetAttribute(k34_softmax_U, cudaFuncAttributeMaxDynamicSharedMemorySize, SMEM_K34);
    cudaFuncSetAttribute(k5_O, cudaFuncAttributeMaxDynamicSharedMemorySize, SMEM_K5);
    cudaFuncSetAttribute(k6_out, cudaFuncAttributeMaxDynamicSharedMemorySize, SMEM_K6);

    kc0<<<3264, 256>>>(inp, Wq, Wk, Wv, aq, ak, av, Wo);
    k1_proj<<<dim3(8, 8, 6), 256>>>();
    k2_J<<<dim3(8, 8, 32), 256>>>();
    k34_softmax_U<<<dim3(1024, 2), 256, SMEM_K34>>>(mask, Wl, Ww);
    k5_O<<<dim3(8, 32), 256, SMEM_K5>>>();
    k6_out<<<dim3(8, 16, 2), 256, SMEM_K6>>>(inp, out);
}